// round 8
// baseline (speedup 1.0000x reference)
#include <cuda_runtime.h>
#include <cuda_bf16.h>
#include <cuda_fp16.h>
#include <math.h>
#include <cstdint>

#define NN 35000
#define NM 80000
#define NBR 6
#define IND 128
#define HD 256
#define DEPTH 5
#define NNP 35072

// ---------------- scratch (__device__ globals; no allocs) ----------------
__device__ float g_fz  [(size_t)NM*HD];
__device__ float g_fh  [(size_t)NM*HD];
__device__ float g_sumh[(size_t)NM*HD];
__device__ float g_sumg[(size_t)NM*HD];
__device__ float g_hA  [(size_t)NM*HD];
__device__ float g_nei [(size_t)NNP*HD];
__device__ __align__(16) __half g_hU16[(size_t)NM*HD];
__device__ __align__(16) __half g_rx16[(size_t)NM*HD];

// transposed+split weights: [N=256, K] bf16, hi and lo planes
#define OFF_WZT 0
#define OFF_WHT 32768
#define OFF_WR  65536
#define OFF_WOT 98304
#define OFF_UR  131072
#define OFF_WZB 196608
#define OFF_WHB 262144
#define OFF_WOB 327680
__device__ __align__(16) __nv_bfloat16 g_bh[393216];
__device__ __align__(16) __nv_bfloat16 g_bl[393216];

__device__ __forceinline__ float sigm(float x){ return 1.0f/(1.0f+expf(-x)); }

// ---------------- mma / ldmatrix / cp.async helpers ----------------------
__device__ __forceinline__ uint32_t smem_addr(const void* p){
    return (uint32_t)__cvta_generic_to_shared(p);
}
__device__ __forceinline__ void ldsm4(uint32_t a, uint32_t& r0, uint32_t& r1,
                                      uint32_t& r2, uint32_t& r3){
    asm volatile("ldmatrix.sync.aligned.m8n8.x4.shared.b16 {%0,%1,%2,%3}, [%4];"
                 : "=r"(r0), "=r"(r1), "=r"(r2), "=r"(r3) : "r"(a));
}
__device__ __forceinline__ void mma16816(float* c, const uint32_t* a, const uint32_t* b){
    asm volatile(
        "mma.sync.aligned.m16n8k16.row.col.f32.bf16.bf16.f32 "
        "{%0,%1,%2,%3}, {%4,%5,%6,%7}, {%8,%9}, {%0,%1,%2,%3};"
        : "+f"(c[0]), "+f"(c[1]), "+f"(c[2]), "+f"(c[3])
        : "r"(a[0]), "r"(a[1]), "r"(a[2]), "r"(a[3]), "r"(b[0]), "r"(b[1]));
}
#define CPA16(dst, src) \
    asm volatile("cp.async.cg.shared.global [%0], [%1], 16;" :: "r"(dst), "l"(src))
#define CP_COMMIT() asm volatile("cp.async.commit_group;" ::: "memory")
#define CP_WAIT0()  asm volatile("cp.async.wait_group 0;" ::: "memory")

__device__ __forceinline__ void cvt_split8(float4 v0, float4 v1, uint4& hi, uint4& lo){
    float f[8] = {v0.x,v0.y,v0.z,v0.w,v1.x,v1.y,v1.z,v1.w};
    uint32_t hh[8], ll[8];
    #pragma unroll
    for (int j = 0; j < 8; ++j) {
        __nv_bfloat16 h = __float2bfloat16_rn(f[j]);
        float hf = __bfloat162float(h);
        __nv_bfloat16 l = __float2bfloat16_rn(f[j] - hf);
        hh[j] = (uint32_t)__bfloat16_as_ushort(h);
        ll[j] = (uint32_t)__bfloat16_as_ushort(l);
    }
    hi = make_uint4(hh[0]|(hh[1]<<16), hh[2]|(hh[3]<<16), hh[4]|(hh[5]<<16), hh[6]|(hh[7]<<16));
    lo = make_uint4(ll[0]|(ll[1]<<16), ll[2]|(ll[3]<<16), ll[4]|(ll[5]<<16), ll[6]|(ll[7]<<16));
}

// smem geometry: rows of PADK=40 bf16 (80 B), chunk = 32 K-cols, NT=256 always
#define PADK 40

// ---- pipelined GEMM phase, MT rows x 256 cols, NA fused operands --------
// acc layout: acc[((op*2 + mi)*NFR + ni)*4 + q], NFR = 256/(16/(MT/32))/8
template<int MT, int NA>
__device__ __forceinline__ void run_phase(
    const float* __restrict__ A1, const float* __restrict__ A2, int K,
    const __nv_bfloat16* __restrict__ B1h, const __nv_bfloat16* __restrict__ B1l,
    const __nv_bfloat16* __restrict__ B2h, const __nv_bfloat16* __restrict__ B2l,
    float* acc, char* sm, int tid, int rowBase, int M)
{
    constexpr int WM = MT/32;                 // 4 or 2
    constexpr int WN = 16/WM;                 // 4 or 8
    constexpr int NSPAN = 256/WN;             // 64 or 32
    constexpr int NFR = NSPAN/8;              // 8 or 4
    constexpr uint32_t APL = MT*80u;          // A plane bytes
    constexpr uint32_t A_BYTES = NA*2u*APL;
    constexpr uint32_t BPL = 20480u;          // 256*80
    constexpr uint32_t STAGE_ = A_BYTES + NA*2u*BPL;
    constexpr int NB = NA*4;
    const int lane = tid & 31, wid = tid >> 5;
    const int wm = wid / WN, wn = wid % WN;
    const int g = lane >> 3, r = lane & 7;
    const uint32_t sb = smem_addr(sm);
    const int nch = K >> 5;

    // A mapping: exactly 1 unit/thread (NA*MT*4 == 512)
    const int a_op  = tid / (MT*4);
    const int a_rem = tid % (MT*4);
    const int a_row = a_rem >> 2, a_seg = a_rem & 3;
    const int grow = rowBase + a_row;
    const bool a_ok = (grow < M);
    const float* a_src = ((a_op == 0) ? A1 : A2) + (size_t)grow*K + (a_seg << 3);
    const uint32_t a_off = (uint32_t)a_op*2u*APL + (uint32_t)a_row*80u + (uint32_t)a_seg*16u;

    // B issue (recomputed per call; cheap ALU)
    auto issue_B = [&](uint32_t st, int c){
        #pragma unroll
        for (int i = 0; i < NB; ++i){
            int idx = tid + (i << 9);
            int op = idx >> 11;
            int rem = idx & 2047;
            int plane = rem >> 10;
            int rem2 = rem & 1023;
            int row = rem2 >> 2, seg = rem2 & 3;
            const __nv_bfloat16* Bp = (op == 0) ? (plane ? B1l : B1h)
                                                : (plane ? B2l : B2h);
            const __nv_bfloat16* src = Bp + (size_t)row*K + (c << 5) + (seg << 3);
            uint32_t dst = st + A_BYTES + (uint32_t)op*(2u*BPL) + (uint32_t)plane*BPL
                         + (uint32_t)row*80u + (uint32_t)seg*16u;
            CPA16(dst, src);
        }
        CP_COMMIT();
    };

    // ---- prologue: stage 0 ----
    {
        float4 v0 = make_float4(0.f,0.f,0.f,0.f), v1 = v0;
        if (a_ok){ v0 = *(const float4*)a_src; v1 = *(const float4*)(a_src + 4); }
        issue_B(sb, 0);
        uint4 hi, lo; cvt_split8(v0, v1, hi, lo);
        *(uint4*)(sm + a_off)       = hi;
        *(uint4*)(sm + a_off + APL) = lo;
        CP_WAIT0();
    }
    __syncthreads();

    for (int c = 0; c < nch; ++c){
        const uint32_t st = sb + (c & 1)*STAGE_;
        const int nc = c + 1;
        float4 v0, v1;
        if (nc < nch){
            v0 = make_float4(0.f,0.f,0.f,0.f); v1 = v0;
            if (a_ok){
                const float* p = a_src + (nc << 5);
                v0 = *(const float4*)p; v1 = *(const float4*)(p + 4);
            }
            issue_B(sb + (nc & 1)*STAGE_, nc);
        }

        // ---- compute on stage c ----
        #pragma unroll
        for (int op = 0; op < NA; ++op){
            const uint32_t aBase = st + (uint32_t)op*2u*APL;
            const uint32_t bBase = st + A_BYTES + (uint32_t)op*(2u*BPL);
            #pragma unroll
            for (int ki = 0; ki < 2; ++ki){
                uint32_t ah[2][4], al[2][4];
                {
                    int arow = wm*32 + (g & 1)*8 + r;
                    uint32_t off = (uint32_t)(arow*PADK + ki*16 + (g >> 1)*8) * 2;
                    ldsm4(aBase + off,                     ah[0][0], ah[0][1], ah[0][2], ah[0][3]);
                    ldsm4(aBase + off + 16*PADK*2,         ah[1][0], ah[1][1], ah[1][2], ah[1][3]);
                    ldsm4(aBase + APL + off,               al[0][0], al[0][1], al[0][2], al[0][3]);
                    ldsm4(aBase + APL + off + 16*PADK*2,   al[1][0], al[1][1], al[1][2], al[1][3]);
                }
                #pragma unroll
                for (int ng = 0; ng < NFR/4; ++ng){
                    uint32_t bhf[4][2], blf[4][2];
                    int nrow = wn*NSPAN + ng*32 + (g >> 1)*8 + r;
                    uint32_t off = (uint32_t)(nrow*PADK + ki*16 + (g & 1)*8) * 2;
                    ldsm4(bBase + off,                 bhf[0][0], bhf[0][1], bhf[1][0], bhf[1][1]);
                    ldsm4(bBase + off + 16*PADK*2,     bhf[2][0], bhf[2][1], bhf[3][0], bhf[3][1]);
                    ldsm4(bBase + BPL + off,             blf[0][0], blf[0][1], blf[1][0], blf[1][1]);
                    ldsm4(bBase + BPL + off + 16*PADK*2, blf[2][0], blf[2][1], blf[3][0], blf[3][1]);
                    #pragma unroll
                    for (int mi = 0; mi < 2; ++mi)
                        #pragma unroll
                        for (int j = 0; j < 4; ++j){
                            float* a = acc + (((op*2 + mi)*NFR) + ng*4 + j)*4;
                            mma16816(a, ah[mi], bhf[j]);
                            mma16816(a, ah[mi], blf[j]);
                            mma16816(a, al[mi], bhf[j]);
                        }
                }
            }
        }

        if (nc < nch){
            char* nsm = sm + (nc & 1)*STAGE_;
            uint4 hi, lo; cvt_split8(v0, v1, hi, lo);
            *(uint4*)(nsm + a_off)       = hi;
            *(uint4*)(nsm + a_off + APL) = lo;
            CP_WAIT0();
        }
        __syncthreads();
    }
}

#define SMEM_M0 (2*(2*128*80 + 2*20480))   // 122880
#define SMEM_M1 (2*(4*64*80 + 4*20480))    // 204800

// MODE0: MT=128, NA=1. C = D + (bias ? bias[col] : 0); OUTF=1 -> fp16 out
template<int OUTF>
__global__ __launch_bounds__(512, 1)
void mode0_gemm(const float* __restrict__ A, int K,
                const __nv_bfloat16* __restrict__ Bh, const __nv_bfloat16* __restrict__ Bl,
                int M, const float* __restrict__ bias, void* __restrict__ Cout)
{
    extern __shared__ char sm[];
    const int tid = threadIdx.x;
    const int rowBase = (int)blockIdx.x << 7;
    const int lane = tid & 31, wid = tid >> 5;
    const int wm = wid >> 2, wn = wid & 3;
    const int tq = lane >> 2, tr = lane & 3;

    float acc[64];
    #pragma unroll
    for (int i = 0; i < 64; ++i) acc[i] = 0.f;

    run_phase<128,1>(A, nullptr, K, Bh, Bl, nullptr, nullptr, acc, sm, tid, rowBase, M);

    #pragma unroll
    for (int mi = 0; mi < 2; ++mi)
        #pragma unroll
        for (int ni = 0; ni < 8; ++ni) {
            const float* a = acc + (mi*8 + ni)*4;
            int gcol = wn*64 + ni*8 + tr*2;
            int r0 = rowBase + wm*32 + mi*16 + tq;
            float bx = 0.f, by = 0.f;
            if (bias) { float2 b = *(const float2*)&bias[gcol]; bx = b.x; by = b.y; }
            if (OUTF == 0) {
                float* C = (float*)Cout;
                *(float2*)&C[(size_t)r0*HD + gcol]     = make_float2(a[0]+bx, a[1]+by);
                *(float2*)&C[(size_t)(r0+8)*HD + gcol] = make_float2(a[2]+bx, a[3]+by);
            } else {
                __half* C = (__half*)Cout;
                *(__half2*)&C[(size_t)r0*HD + gcol]     = __floats2half2_rn(a[0]+bx, a[1]+by);
                *(__half2*)&C[(size_t)(r0+8)*HD + gcol] = __floats2half2_rn(a[2]+bx, a[3]+by);
            }
        }
}

// MODE1: MT=64, NA=2, full N=256. z=sig(fz+D1), p=tanh(fh+D2);
//        C = ((1-z)*sumh + z*p), row 0 forced to 0
__global__ __launch_bounds__(512, 1)
void mode1_gemm(const float* __restrict__ A1,
                const __nv_bfloat16* __restrict__ B1h, const __nv_bfloat16* __restrict__ B1l,
                const float* __restrict__ A2,
                const __nv_bfloat16* __restrict__ B2h, const __nv_bfloat16* __restrict__ B2l,
                const float* __restrict__ e0, const float* __restrict__ e1,
                const float* __restrict__ e2, float* __restrict__ C)
{
    extern __shared__ char sm[];
    const int tid = threadIdx.x;
    const int rowBase = (int)blockIdx.x << 6;
    const int lane = tid & 31, wid = tid >> 5;
    const int wm = wid >> 3, wn = wid & 7;      // 2 x 8 warps
    const int tq = lane >> 2, tr = lane & 3;

    float acc[64];
    #pragma unroll
    for (int i = 0; i < 64; ++i) acc[i] = 0.f;

    run_phase<64,2>(A1, A2, HD, B1h, B1l, B2h, B2l, acc, sm, tid, rowBase, NM);

    #pragma unroll
    for (int mi = 0; mi < 2; ++mi)
        #pragma unroll
        for (int ni = 0; ni < 4; ++ni) {
            const float* a1 = acc + ((0*2 + mi)*4 + ni)*4;
            const float* a2 = acc + ((1*2 + mi)*4 + ni)*4;
            int gcol = wn*32 + ni*8 + tr*2;
            int r0 = rowBase + wm*32 + mi*16 + tq;
            size_t o0 = (size_t)r0*HD + gcol;
            size_t o1 = (size_t)(r0+8)*HD + gcol;
            float2 za = *(const float2*)&e0[o0];
            float2 zb = *(const float2*)&e0[o1];
            float2 ha = *(const float2*)&e1[o0];
            float2 hb = *(const float2*)&e1[o1];
            float2 sa = *(const float2*)&e2[o0];
            float2 sb = *(const float2*)&e2[o1];
            float z0 = sigm(za.x + a1[0]);
            float z1 = sigm(za.y + a1[1]);
            float z2 = sigm(zb.x + a1[2]);
            float z3 = sigm(zb.y + a1[3]);
            float p0 = tanhf(ha.x + a2[0]);
            float p1 = tanhf(ha.y + a2[1]);
            float p2 = tanhf(hb.x + a2[2]);
            float p3 = tanhf(hb.y + a2[3]);
            float2 u0 = make_float2((1.f - z0)*sa.x + z0*p0, (1.f - z1)*sa.y + z1*p1);
            float2 u1 = make_float2((1.f - z2)*sb.x + z2*p2, (1.f - z3)*sb.y + z3*p3);
            if (r0 == 0) u0 = make_float2(0.f, 0.f);   // null message row
            *(float2*)&C[o0] = u0;
            *(float2*)&C[o1] = u1;
        }
}

// MODE2: MT=128, two accumulating phases. C = relu(D+b[col])*mask[row]
__global__ __launch_bounds__(512, 1)
void mode2_gemm(const float* __restrict__ A1, int K1,
                const __nv_bfloat16* __restrict__ B1h, const __nv_bfloat16* __restrict__ B1l,
                const float* __restrict__ A2, int K2,
                const __nv_bfloat16* __restrict__ B2h, const __nv_bfloat16* __restrict__ B2l,
                int M, const float* __restrict__ bias, const float* __restrict__ maskv,
                float* __restrict__ C)
{
    extern __shared__ char sm[];
    const int tid = threadIdx.x;
    const int rowBase = (int)blockIdx.x << 7;
    const int lane = tid & 31, wid = tid >> 5;
    const int wm = wid >> 2, wn = wid & 3;
    const int tq = lane >> 2, tr = lane & 3;

    float acc[64];
    #pragma unroll
    for (int i = 0; i < 64; ++i) acc[i] = 0.f;

    run_phase<128,1>(A1, nullptr, K1, B1h, B1l, nullptr, nullptr, acc, sm, tid, rowBase, M);
    run_phase<128,1>(A2, nullptr, K2, B2h, B2l, nullptr, nullptr, acc, sm, tid, rowBase, M);

    #pragma unroll
    for (int mi = 0; mi < 2; ++mi)
        #pragma unroll
        for (int ni = 0; ni < 8; ++ni) {
            const float* a = acc + (mi*8 + ni)*4;
            int gcol = wn*64 + ni*8 + tr*2;
            int r0 = rowBase + wm*32 + mi*16 + tq;
            float2 b = *(const float2*)&bias[gcol];
            if (r0 < M) {
                float m = maskv[r0];
                *(float2*)&C[(size_t)r0*HD + gcol] =
                    make_float2(fmaxf(a[0]+b.x, 0.f)*m, fmaxf(a[1]+b.y, 0.f)*m);
            }
            if (r0 + 8 < M) {
                float m = maskv[r0+8];
                *(float2*)&C[(size_t)(r0+8)*HD + gcol] =
                    make_float2(fmaxf(a[2]+b.x, 0.f)*m, fmaxf(a[3]+b.y, 0.f)*m);
            }
        }
}

// transpose + bf16 hi/lo split of W[K,256] -> out[N=256, K]
__global__ void prep_w(const float* __restrict__ W, __nv_bfloat16* __restrict__ oh,
                       __nv_bfloat16* __restrict__ ol, int K, int kshift)
{
    int i = blockIdx.x * blockDim.x + threadIdx.x;
    int k = i & (K - 1);
    int n = i >> kshift;
    float x = W[(size_t)k * HD + n];
    __nv_bfloat16 h = __float2bfloat16_rn(x);
    __nv_bfloat16 lo = __float2bfloat16_rn(x - __bfloat162float(h));
    oh[i] = h; ol[i] = lo;
}

// Step 1 (h=0): h1 = sigmoid(fz)*tanh(fh), row 0 masked.
__global__ void first_step(const float4* __restrict__ fz, const float4* __restrict__ fh,
                           float4* __restrict__ h1)
{
    size_t i = blockIdx.x*(size_t)blockDim.x + threadIdx.x;
    float4 z = fz[i], h = fh[i];
    float4 o;
    o.x = sigm(z.x)*tanhf(h.x);
    o.y = sigm(z.y)*tanhf(h.y);
    o.z = sigm(z.z)*tanhf(h.z);
    o.w = sigm(z.w)*tanhf(h.w);
    if (i < HD/4) o = make_float4(0.f,0.f,0.f,0.f);
    h1[i] = o;
}

__global__ void gather_msgs(const float* __restrict__ h, const __half* __restrict__ hU,
                            const __half* __restrict__ rx, const int* __restrict__ bg,
                            float* __restrict__ sumh, float* __restrict__ sumg)
{
    __shared__ int s_nb[4][NBR];
    int e = blockIdx.x * 4 + threadIdx.y;
    if (threadIdx.x < NBR) s_nb[threadIdx.y][threadIdx.x] = bg[e*NBR + threadIdx.x];
    __syncthreads();
    int c = threadIdx.x << 2;
    size_t base = (size_t)e*HD + c;
    uint2 rx4 = *(const uint2*)(rx + base);
    float2 r01 = __half22float2(*reinterpret_cast<__half2*>(&rx4.x));
    float2 r23 = __half22float2(*reinterpret_cast<__half2*>(&rx4.y));
    float4 sh = make_float4(0.f,0.f,0.f,0.f);
    float4 sg = make_float4(0.f,0.f,0.f,0.f);
    #pragma unroll
    for (int j = 0; j < NBR; ++j) {
        size_t nb = (size_t)s_nb[threadIdx.y][j]*HD + c;
        float4 hv = *(const float4*)&h[nb];
        uint2 hu4 = *(const uint2*)(hU + nb);
        float2 u01 = __half22float2(*reinterpret_cast<__half2*>(&hu4.x));
        float2 u23 = __half22float2(*reinterpret_cast<__half2*>(&hu4.y));
        sh.x += hv.x; sh.y += hv.y; sh.z += hv.z; sh.w += hv.w;
        sg.x += sigm(r01.x + u01.x) * hv.x;
        sg.y += sigm(r01.y + u01.y) * hv.y;
        sg.z += sigm(r23.x + u23.x) * hv.z;
        sg.w += sigm(r23.y + u23.y) * hv.w;
    }
    *(float4*)&sumh[base] = sh;
    *(float4*)&sumg[base] = sg;
}

__global__ void gather_nodes(const float* __restrict__ h, const int* __restrict__ ag,
                             float* __restrict__ nei)
{
    __shared__ int s_nb[4][NBR];
    int v = blockIdx.x * 4 + threadIdx.y;
    if (threadIdx.x < NBR) s_nb[threadIdx.y][threadIdx.x] = ag[v*NBR + threadIdx.x];
    __syncthreads();
    int c = threadIdx.x << 2;
    float4 s = make_float4(0.f,0.f,0.f,0.f);
    #pragma unroll
    for (int j = 0; j < NBR; ++j) {
        size_t nb = (size_t)s_nb[threadIdx.y][j]*HD + c;
        float4 hv = *(const float4*)&h[nb];
        s.x += hv.x; s.y += hv.y; s.z += hv.z; s.w += hv.w;
    }
    *(float4*)&nei[(size_t)v*HD + c] = s;
}

extern "C" void kernel_launch(void* const* d_in, const int* in_sizes, int n_in,
                              void* d_out, int out_size)
{
    const float* fnode  = (const float*)d_in[0];
    const float* fmess  = (const float*)d_in[1];
    const int*   agraph = (const int*)  d_in[2];
    const int*   bgraph = (const int*)  d_in[3];
    const float* mask   = (const float*)d_in[4];
    const float* W_z    = (const float*)d_in[5];
    const float* b_z    = (const float*)d_in[6];
    const float* W_r    = (const float*)d_in[7];
    const float* U_r    = (const float*)d_in[8];
    const float* b_ur   = (const float*)d_in[9];
    const float* W_h    = (const float*)d_in[10];
    const float* b_h    = (const float*)d_in[11];
    const float* W_o    = (const float*)d_in[12];
    const float* b_o    = (const float*)d_in[13];

    float* out_node = (float*)d_out;
    float* out_h    = out_node + (size_t)NN*HD;

    float *fz, *fh, *sumh, *sumg, *hA, *nei;
    __half *hU16, *rx16;
    __nv_bfloat16 *bh, *bl;
    cudaGetSymbolAddress((void**)&fz,   g_fz);
    cudaGetSymbolAddress((void**)&fh,   g_fh);
    cudaGetSymbolAddress((void**)&sumh, g_sumh);
    cudaGetSymbolAddress((void**)&sumg, g_sumg);
    cudaGetSymbolAddress((void**)&hA,   g_hA);
    cudaGetSymbolAddress((void**)&nei,  g_nei);
    cudaGetSymbolAddress((void**)&hU16, g_hU16);
    cudaGetSymbolAddress((void**)&rx16, g_rx16);
    cudaGetSymbolAddress((void**)&bh,   g_bh);
    cudaGetSymbolAddress((void**)&bl,   g_bl);

    cudaFuncSetAttribute((const void*)mode0_gemm<0>,
                         cudaFuncAttributeMaxDynamicSharedMemorySize, SMEM_M0);
    cudaFuncSetAttribute((const void*)mode0_gemm<1>,
                         cudaFuncAttributeMaxDynamicSharedMemorySize, SMEM_M0);
    cudaFuncSetAttribute((const void*)mode1_gemm,
                         cudaFuncAttributeMaxDynamicSharedMemorySize, SMEM_M1);
    cudaFuncSetAttribute((const void*)mode2_gemm,
                         cudaFuncAttributeMaxDynamicSharedMemorySize, SMEM_M0);

    const int gE128 = NM / 128;               // 625
    const int gE64  = NM / 64;                // 1250
    const int gV    = NNP / 128;              // 274

    // preps needed by the invariant GEMMs first (launches 1-3), then the three
    // invariant GEMMs (4-6) so ncu's "-s 5 -c 1" profiles a real GEMM (launch 6)
    prep_w<<<128, 256>>>(W_z, bh+OFF_WZT, bl+OFF_WZT, IND, 7);
    prep_w<<<128, 256>>>(W_h, bh+OFF_WHT, bl+OFF_WHT, IND, 7);
    prep_w<<<128, 256>>>(W_r, bh+OFF_WR,  bl+OFF_WR,  IND, 7);

    mode0_gemm<0><<<gE128, 512, SMEM_M0>>>(fmess, IND, bh+OFF_WZT, bl+OFF_WZT,
                                           NM, b_z, fz);
    mode0_gemm<0><<<gE128, 512, SMEM_M0>>>(fmess, IND, bh+OFF_WHT, bl+OFF_WHT,
                                           NM, b_h, fh);
    mode0_gemm<1><<<gE128, 512, SMEM_M0>>>(fmess, IND, bh+OFF_WR, bl+OFF_WR,
                                           NM, b_ur, rx16);     // <- profiled

    // remaining weight preps
    prep_w<<<256, 256>>>(U_r,                  bh+OFF_UR,  bl+OFF_UR,  HD, 8);
    prep_w<<<256, 256>>>(W_z + (size_t)IND*HD, bh+OFF_WZB, bl+OFF_WZB, HD, 8);
    prep_w<<<256, 256>>>(W_h + (size_t)IND*HD, bh+OFF_WHB, bl+OFF_WHB, HD, 8);
    prep_w<<<128, 256>>>(W_o,                  bh+OFF_WOT, bl+OFF_WOT, IND, 7);
    prep_w<<<256, 256>>>(W_o + (size_t)IND*HD, bh+OFF_WOB, bl+OFF_WOB, HD, 8);

    // step 1 (h=0) is elementwise
    first_step<<<(NM*HD/4)/256, 256>>>((const float4*)fz, (const float4*)fh, (float4*)out_h);

    float* hc = out_h;
    float* hn = hA;
    for (int d = 1; d < DEPTH; ++d) {
        mode0_gemm<1><<<gE128, 512, SMEM_M0>>>(hc, HD, bh+OFF_UR, bl+OFF_UR,
                                               NM, nullptr, hU16);
        gather_msgs<<<NM/4, dim3(64,4)>>>(hc, hU16, rx16, bgraph, sumh, sumg);
        mode1_gemm<<<gE64, 512, SMEM_M1>>>(sumh, bh+OFF_WZB, bl+OFF_WZB,
                                           sumg, bh+OFF_WHB, bl+OFF_WHB,
                                           fz, fh, sumh, hn);
        float* t = hc; hc = hn; hn = t;
    }

    gather_nodes<<<NN/4, dim3(64,4)>>>(hc, agraph, nei);
    mode2_gemm<<<gV, 512, SMEM_M0>>>(fnode, IND, bh+OFF_WOT, bl+OFF_WOT,
                                     nei, HD, bh+OFF_WOB, bl+OFF_WOB,
                                     NN, b_o, mask, out_node);
}

// round 9
// speedup vs baseline: 1.1121x; 1.1121x over previous
#include <cuda_runtime.h>
#include <cuda_bf16.h>
#include <cuda_fp16.h>
#include <math.h>
#include <cstdint>

#define NN 35000
#define NM 80000
#define NBR 6
#define IND 128
#define HD 256
#define DEPTH 5
#define NNP 35072

// ---------------- scratch (__device__ globals; no allocs) ----------------
__device__ float g_fz  [(size_t)NM*HD];
__device__ float g_fh  [(size_t)NM*HD];
__device__ float g_sumh[(size_t)NM*HD];
__device__ float g_sumg[(size_t)NM*HD];
__device__ float g_hA  [(size_t)NM*HD];
__device__ float g_nei [(size_t)NNP*HD];
__device__ __align__(16) __half g_hU16[(size_t)NM*HD];
__device__ __align__(16) __half g_rx16[(size_t)NM*HD];

// transposed+split weights: [N=256, K] bf16, hi and lo planes
#define OFF_WZT 0
#define OFF_WHT 32768
#define OFF_WR  65536
#define OFF_WOT 98304
#define OFF_UR  131072
#define OFF_WZB 196608
#define OFF_WHB 262144
#define OFF_WOB 327680
__device__ __align__(16) __nv_bfloat16 g_bh[393216];
__device__ __align__(16) __nv_bfloat16 g_bl[393216];

__device__ __forceinline__ float sigm(float x){ return 1.0f/(1.0f+expf(-x)); }

// ---------------- mma / ldmatrix / cp.async helpers ----------------------
__device__ __forceinline__ uint32_t smem_addr(const void* p){
    return (uint32_t)__cvta_generic_to_shared(p);
}
__device__ __forceinline__ void ldsm4(uint32_t a, uint32_t& r0, uint32_t& r1,
                                      uint32_t& r2, uint32_t& r3){
    asm volatile("ldmatrix.sync.aligned.m8n8.x4.shared.b16 {%0,%1,%2,%3}, [%4];"
                 : "=r"(r0), "=r"(r1), "=r"(r2), "=r"(r3) : "r"(a));
}
__device__ __forceinline__ void mma16816(float* c, const uint32_t* a, const uint32_t* b){
    asm volatile(
        "mma.sync.aligned.m16n8k16.row.col.f32.bf16.bf16.f32 "
        "{%0,%1,%2,%3}, {%4,%5,%6,%7}, {%8,%9}, {%0,%1,%2,%3};"
        : "+f"(c[0]), "+f"(c[1]), "+f"(c[2]), "+f"(c[3])
        : "r"(a[0]), "r"(a[1]), "r"(a[2]), "r"(a[3]), "r"(b[0]), "r"(b[1]));
}
#define CPA16(dst, src) \
    asm volatile("cp.async.cg.shared.global [%0], [%1], 16;" :: "r"(dst), "l"(src))
#define CP_COMMIT() asm volatile("cp.async.commit_group;" ::: "memory")
#define CP_WAIT0()  asm volatile("cp.async.wait_group 0;" ::: "memory")

__device__ __forceinline__ void cvt_split8(float4 v0, float4 v1, uint4& hi, uint4& lo){
    float f[8] = {v0.x,v0.y,v0.z,v0.w,v1.x,v1.y,v1.z,v1.w};
    uint32_t hh[8], ll[8];
    #pragma unroll
    for (int j = 0; j < 8; ++j) {
        __nv_bfloat16 h = __float2bfloat16_rn(f[j]);
        float hf = __bfloat162float(h);
        __nv_bfloat16 l = __float2bfloat16_rn(f[j] - hf);
        hh[j] = (uint32_t)__bfloat16_as_ushort(h);
        ll[j] = (uint32_t)__bfloat16_as_ushort(l);
    }
    hi = make_uint4(hh[0]|(hh[1]<<16), hh[2]|(hh[3]<<16), hh[4]|(hh[5]<<16), hh[6]|(hh[7]<<16));
    lo = make_uint4(ll[0]|(ll[1]<<16), ll[2]|(ll[3]<<16), ll[4]|(ll[5]<<16), ll[6]|(ll[7]<<16));
}
__device__ __forceinline__ uint4 cvt_hi8(float4 v0, float4 v1){
    float f[8] = {v0.x,v0.y,v0.z,v0.w,v1.x,v1.y,v1.z,v1.w};
    uint32_t hh[8];
    #pragma unroll
    for (int j = 0; j < 8; ++j)
        hh[j] = (uint32_t)__bfloat16_as_ushort(__float2bfloat16_rn(f[j]));
    return make_uint4(hh[0]|(hh[1]<<16), hh[2]|(hh[3]<<16), hh[4]|(hh[5]<<16), hh[6]|(hh[7]<<16));
}

#define PADK 40

// ================= 3-pass pipelined phase (from R8; MODE1/MODE2) =========
template<int MT, int NA>
__device__ __forceinline__ void run_phase(
    const float* __restrict__ A1, const float* __restrict__ A2, int K,
    const __nv_bfloat16* __restrict__ B1h, const __nv_bfloat16* __restrict__ B1l,
    const __nv_bfloat16* __restrict__ B2h, const __nv_bfloat16* __restrict__ B2l,
    float* acc, char* sm, int tid, int rowBase, int M)
{
    constexpr int WM = MT/32;
    constexpr int WN = 16/WM;
    constexpr int NSPAN = 256/WN;
    constexpr int NFR = NSPAN/8;
    constexpr uint32_t APL = MT*80u;
    constexpr uint32_t A_BYTES = NA*2u*APL;
    constexpr uint32_t BPL = 20480u;
    constexpr uint32_t STAGE_ = A_BYTES + NA*2u*BPL;
    constexpr int NB = NA*4;
    const int lane = tid & 31, wid = tid >> 5;
    const int wm = wid / WN, wn = wid % WN;
    const int g = lane >> 3, r = lane & 7;
    const uint32_t sb = smem_addr(sm);
    const int nch = K >> 5;

    const int a_op  = tid / (MT*4);
    const int a_rem = tid % (MT*4);
    const int a_row = a_rem >> 2, a_seg = a_rem & 3;
    const int grow = rowBase + a_row;
    const bool a_ok = (grow < M);
    const float* a_src = ((a_op == 0) ? A1 : A2) + (size_t)grow*K + (a_seg << 3);
    const uint32_t a_off = (uint32_t)a_op*2u*APL + (uint32_t)a_row*80u + (uint32_t)a_seg*16u;

    auto issue_B = [&](uint32_t st, int c){
        #pragma unroll
        for (int i = 0; i < NB; ++i){
            int idx = tid + (i << 9);
            int op = idx >> 11;
            int rem = idx & 2047;
            int plane = rem >> 10;
            int rem2 = rem & 1023;
            int row = rem2 >> 2, seg = rem2 & 3;
            const __nv_bfloat16* Bp = (op == 0) ? (plane ? B1l : B1h)
                                                : (plane ? B2l : B2h);
            const __nv_bfloat16* src = Bp + (size_t)row*K + (c << 5) + (seg << 3);
            uint32_t dst = st + A_BYTES + (uint32_t)op*(2u*BPL) + (uint32_t)plane*BPL
                         + (uint32_t)row*80u + (uint32_t)seg*16u;
            CPA16(dst, src);
        }
        CP_COMMIT();
    };

    {
        float4 v0 = make_float4(0.f,0.f,0.f,0.f), v1 = v0;
        if (a_ok){ v0 = *(const float4*)a_src; v1 = *(const float4*)(a_src + 4); }
        issue_B(sb, 0);
        uint4 hi, lo; cvt_split8(v0, v1, hi, lo);
        *(uint4*)(sm + a_off)       = hi;
        *(uint4*)(sm + a_off + APL) = lo;
        CP_WAIT0();
    }
    __syncthreads();

    for (int c = 0; c < nch; ++c){
        const uint32_t st = sb + (c & 1)*STAGE_;
        const int nc = c + 1;
        float4 v0, v1;
        if (nc < nch){
            v0 = make_float4(0.f,0.f,0.f,0.f); v1 = v0;
            if (a_ok){
                const float* p = a_src + (nc << 5);
                v0 = *(const float4*)p; v1 = *(const float4*)(p + 4);
            }
            issue_B(sb + (nc & 1)*STAGE_, nc);
        }

        #pragma unroll
        for (int op = 0; op < NA; ++op){
            const uint32_t aBase = st + (uint32_t)op*2u*APL;
            const uint32_t bBase = st + A_BYTES + (uint32_t)op*(2u*BPL);
            #pragma unroll
            for (int ki = 0; ki < 2; ++ki){
                uint32_t ah[2][4], al[2][4];
                {
                    int arow = wm*32 + (g & 1)*8 + r;
                    uint32_t off = (uint32_t)(arow*PADK + ki*16 + (g >> 1)*8) * 2;
                    ldsm4(aBase + off,                   ah[0][0], ah[0][1], ah[0][2], ah[0][3]);
                    ldsm4(aBase + off + 16*PADK*2,       ah[1][0], ah[1][1], ah[1][2], ah[1][3]);
                    ldsm4(aBase + APL + off,             al[0][0], al[0][1], al[0][2], al[0][3]);
                    ldsm4(aBase + APL + off + 16*PADK*2, al[1][0], al[1][1], al[1][2], al[1][3]);
                }
                #pragma unroll
                for (int ng = 0; ng < NFR/4; ++ng){
                    uint32_t bhf[4][2], blf[4][2];
                    int nrow = wn*NSPAN + ng*32 + (g >> 1)*8 + r;
                    uint32_t off = (uint32_t)(nrow*PADK + ki*16 + (g & 1)*8) * 2;
                    ldsm4(bBase + off,                 bhf[0][0], bhf[0][1], bhf[1][0], bhf[1][1]);
                    ldsm4(bBase + off + 16*PADK*2,     bhf[2][0], bhf[2][1], bhf[3][0], bhf[3][1]);
                    ldsm4(bBase + BPL + off,             blf[0][0], blf[0][1], blf[1][0], blf[1][1]);
                    ldsm4(bBase + BPL + off + 16*PADK*2, blf[2][0], blf[2][1], blf[3][0], blf[3][1]);
                    #pragma unroll
                    for (int mi = 0; mi < 2; ++mi)
                        #pragma unroll
                        for (int j = 0; j < 4; ++j){
                            float* a = acc + (((op*2 + mi)*NFR) + ng*4 + j)*4;
                            mma16816(a, ah[mi], bhf[j]);
                            mma16816(a, ah[mi], blf[j]);
                            mma16816(a, al[mi], bhf[j]);
                        }
                }
            }
        }

        if (nc < nch){
            char* nsm = sm + (nc & 1)*STAGE_;
            uint4 hi, lo; cvt_split8(v0, v1, hi, lo);
            *(uint4*)(nsm + a_off)       = hi;
            *(uint4*)(nsm + a_off + APL) = lo;
            CP_WAIT0();
        }
        __syncthreads();
    }
}

#define SMEM_M0 (2*(2*128*80 + 2*20480))   // 122880
#define SMEM_M1 (2*(4*64*80 + 4*20480))    // 204800
#define SMEM_HU (2*(128*80 + 20480))       // 61440
#define SMEM_I3 (4*20480 + 2*40960)        // 163840

// ================= single-pass bf16 GEMM for hU (gate path) ==============
// hU = h @ U_r (plain bf16, 1 MMA pass), out fp16. M = NM (multiple of 128).
__global__ __launch_bounds__(512, 1)
void hU_gemm(const float* __restrict__ A, const __nv_bfloat16* __restrict__ Bh,
             __half* __restrict__ Cout)
{
    constexpr int K = HD;
    constexpr uint32_t APL = 10240u, STAGE_ = 30720u;
    extern __shared__ char sm[];
    const int tid = threadIdx.x;
    const int rowBase = (int)blockIdx.x << 7;
    const int lane = tid & 31, wid = tid >> 5;
    const int wm = wid >> 2, wn = wid & 3;
    const int g = lane >> 3, r = lane & 7;
    const int tq = lane >> 2, tr = lane & 3;
    const uint32_t sb = smem_addr(sm);
    const int nch = K >> 5;   // 8

    const int a_row = tid >> 2, a_seg = tid & 3;
    const float* a_src = A + (size_t)(rowBase + a_row)*K + (a_seg << 3);
    const uint32_t a_off = (uint32_t)a_row*80u + (uint32_t)a_seg*16u;

    auto issue_B = [&](uint32_t st, int c){
        #pragma unroll
        for (int i = 0; i < 2; ++i){
            int idx = tid + (i << 9);
            int row = idx >> 2, seg = idx & 3;
            CPA16(st + APL + (uint32_t)row*80u + (uint32_t)seg*16u,
                  Bh + (size_t)row*K + (c << 5) + (seg << 3));
        }
        CP_COMMIT();
    };

    float acc[64];
    #pragma unroll
    for (int i = 0; i < 64; ++i) acc[i] = 0.f;

    {
        float4 v0 = *(const float4*)a_src;
        float4 v1 = *(const float4*)(a_src + 4);
        issue_B(sb, 0);
        *(uint4*)(sm + a_off) = cvt_hi8(v0, v1);
        CP_WAIT0();
    }
    __syncthreads();

    for (int c = 0; c < nch; ++c){
        const uint32_t st = sb + (c & 1)*STAGE_;
        const int nc = c + 1;
        float4 v0, v1;
        if (nc < nch){
            const float* p = a_src + (nc << 5);
            v0 = *(const float4*)p; v1 = *(const float4*)(p + 4);
            issue_B(sb + (nc & 1)*STAGE_, nc);
        }

        #pragma unroll
        for (int ki = 0; ki < 2; ++ki){
            uint32_t ah[2][4];
            {
                int arow = wm*32 + (g & 1)*8 + r;
                uint32_t off = (uint32_t)(arow*PADK + ki*16 + (g >> 1)*8) * 2;
                ldsm4(st + off,             ah[0][0], ah[0][1], ah[0][2], ah[0][3]);
                ldsm4(st + off + 16*PADK*2, ah[1][0], ah[1][1], ah[1][2], ah[1][3]);
            }
            #pragma unroll
            for (int ng = 0; ng < 2; ++ng){
                uint32_t bhf[4][2];
                int nrow = wn*64 + ng*32 + (g >> 1)*8 + r;
                uint32_t off = (uint32_t)(nrow*PADK + ki*16 + (g & 1)*8) * 2;
                ldsm4(st + APL + off,             bhf[0][0], bhf[0][1], bhf[1][0], bhf[1][1]);
                ldsm4(st + APL + off + 16*PADK*2, bhf[2][0], bhf[2][1], bhf[3][0], bhf[3][1]);
                #pragma unroll
                for (int mi = 0; mi < 2; ++mi)
                    #pragma unroll
                    for (int j = 0; j < 4; ++j)
                        mma16816(acc + ((mi*8) + ng*4 + j)*4, ah[mi], bhf[j]);
            }
        }

        if (nc < nch){
            *(uint4*)(sm + (nc & 1)*STAGE_ + a_off) = cvt_hi8(v0, v1);
            CP_WAIT0();
        }
        __syncthreads();
    }

    #pragma unroll
    for (int mi = 0; mi < 2; ++mi)
        #pragma unroll
        for (int ni = 0; ni < 8; ++ni){
            const float* a = acc + (mi*8 + ni)*4;
            int gcol = wn*64 + ni*8 + tr*2;
            int r0 = rowBase + wm*32 + mi*16 + tq;
            *(__half2*)&Cout[(size_t)r0*HD + gcol]     = __floats2half2_rn(a[0], a[1]);
            *(__half2*)&Cout[(size_t)(r0+8)*HD + gcol] = __floats2half2_rn(a[2], a[3]);
        }
}

// ================= fused invariant kernel: fz, fh(+h1), rx ===============
// A = fmess [NM,128] resident in smem (hi/lo, 4 chunk-tiles); 3 B streams.
__global__ __launch_bounds__(512, 1)
void inv3_gemm(const float* __restrict__ A,
               const __nv_bfloat16* __restrict__ Wzh, const __nv_bfloat16* __restrict__ Wzl,
               const __nv_bfloat16* __restrict__ Whh, const __nv_bfloat16* __restrict__ Whl,
               const __nv_bfloat16* __restrict__ Wrh, const __nv_bfloat16* __restrict__ Wrl,
               const float* __restrict__ b_z, const float* __restrict__ b_h,
               const float* __restrict__ b_ur,
               float* __restrict__ fz, float* __restrict__ fh,
               float* __restrict__ h1, __half* __restrict__ rx)
{
    constexpr int K = IND;                 // 128, 4 chunks
    constexpr uint32_t B_OFF = 81920u;     // A region: 4 chunks x 20480
    constexpr uint32_t BPL = 20480u, BSTG = 40960u;
    extern __shared__ char sm[];
    const int tid = threadIdx.x;
    const int rowBase = (int)blockIdx.x << 7;
    const int lane = tid & 31, wid = tid >> 5;
    const int wm = wid >> 2, wn = wid & 3;
    const int g = lane >> 3, r = lane & 7;
    const int tq = lane >> 2, tr = lane & 3;
    const uint32_t sb = smem_addr(sm);

    // ---- load + split A once: 128 rows x 16 groups of 8 ----
    #pragma unroll
    for (int u = 0; u < 4; ++u){
        int idx = tid + (u << 9);
        int row = idx >> 4, gi = idx & 15;
        int t = gi >> 2, seg = gi & 3;
        const float* p = A + (size_t)(rowBase + row)*K + (gi << 3);
        float4 v0 = *(const float4*)p, v1 = *(const float4*)(p + 4);
        uint4 hi, lo; cvt_split8(v0, v1, hi, lo);
        uint32_t off = (uint32_t)t*20480u + (uint32_t)row*80u + (uint32_t)seg*16u;
        *(uint4*)(sm + off)          = hi;
        *(uint4*)(sm + off + 10240u) = lo;
    }
    __syncthreads();

    const __nv_bfloat16* Bhs[3] = {Wzh, Whh, Wrh};
    const __nv_bfloat16* Bls[3] = {Wzl, Whl, Wrl};
    const float* biases[3] = {b_z, b_h, b_ur};

    #pragma unroll
    for (int op = 0; op < 3; ++op){
        const __nv_bfloat16* Bh = Bhs[op];
        const __nv_bfloat16* Bl = Bls[op];

        auto issue_B = [&](uint32_t st, int c){
            #pragma unroll
            for (int i = 0; i < 4; ++i){
                int idx = tid + (i << 9);
                int plane = idx >> 10;
                int rem = idx & 1023;
                int row = rem >> 2, seg = rem & 3;
                const __nv_bfloat16* src = (plane ? Bl : Bh)
                    + (size_t)row*K + (c << 5) + (seg << 3);
                CPA16(st + (uint32_t)plane*BPL + (uint32_t)row*80u + (uint32_t)seg*16u, src);
            }
            CP_COMMIT();
        };

        float acc[64];
        #pragma unroll
        for (int i = 0; i < 64; ++i) acc[i] = 0.f;

        issue_B(sb + B_OFF, 0);
        CP_WAIT0();
        __syncthreads();

        for (int c = 0; c < 4; ++c){
            const uint32_t aBase = sb + (uint32_t)c*20480u;
            const uint32_t bBase = sb + B_OFF + (uint32_t)(c & 1)*BSTG;
            if (c + 1 < 4) issue_B(sb + B_OFF + (uint32_t)((c+1) & 1)*BSTG, c+1);

            #pragma unroll
            for (int ki = 0; ki < 2; ++ki){
                uint32_t ah[2][4], al[2][4];
                {
                    int arow = wm*32 + (g & 1)*8 + r;
                    uint32_t off = (uint32_t)(arow*PADK + ki*16 + (g >> 1)*8) * 2;
                    ldsm4(aBase + off,                  ah[0][0], ah[0][1], ah[0][2], ah[0][3]);
                    ldsm4(aBase + off + 16*PADK*2,      ah[1][0], ah[1][1], ah[1][2], ah[1][3]);
                    ldsm4(aBase + 10240u + off,             al[0][0], al[0][1], al[0][2], al[0][3]);
                    ldsm4(aBase + 10240u + off + 16*PADK*2, al[1][0], al[1][1], al[1][2], al[1][3]);
                }
                #pragma unroll
                for (int ng = 0; ng < 2; ++ng){
                    uint32_t bhf[4][2], blf[4][2];
                    int nrow = wn*64 + ng*32 + (g >> 1)*8 + r;
                    uint32_t off = (uint32_t)(nrow*PADK + ki*16 + (g & 1)*8) * 2;
                    ldsm4(bBase + off,                 bhf[0][0], bhf[0][1], bhf[1][0], bhf[1][1]);
                    ldsm4(bBase + off + 16*PADK*2,     bhf[2][0], bhf[2][1], bhf[3][0], bhf[3][1]);
                    ldsm4(bBase + BPL + off,             blf[0][0], blf[0][1], blf[1][0], blf[1][1]);
                    ldsm4(bBase + BPL + off + 16*PADK*2, blf[2][0], blf[2][1], blf[3][0], blf[3][1]);
                    #pragma unroll
                    for (int mi = 0; mi < 2; ++mi)
                        #pragma unroll
                        for (int j = 0; j < 4; ++j){
                            float* a = acc + ((mi*8) + ng*4 + j)*4;
                            mma16816(a, ah[mi], bhf[j]);
                            mma16816(a, ah[mi], blf[j]);
                            mma16816(a, al[mi], bhf[j]);
                        }
                }
            }
            if (c + 1 < 4) CP_WAIT0();
            __syncthreads();
        }

        // epilogue for this op
        #pragma unroll
        for (int mi = 0; mi < 2; ++mi)
            #pragma unroll
            for (int ni = 0; ni < 8; ++ni){
                const float* a = acc + (mi*8 + ni)*4;
                int gcol = wn*64 + ni*8 + tr*2;
                int r0 = rowBase + wm*32 + mi*16 + tq;
                float2 b = *(const float2*)&biases[op][gcol];
                size_t o0 = (size_t)r0*HD + gcol;
                size_t o1 = (size_t)(r0+8)*HD + gcol;
                float2 u0 = make_float2(a[0]+b.x, a[1]+b.y);
                float2 u1 = make_float2(a[2]+b.x, a[3]+b.y);
                if (op == 0) {
                    *(float2*)&fz[o0] = u0;
                    *(float2*)&fz[o1] = u1;
                } else if (op == 1) {
                    *(float2*)&fh[o0] = u0;
                    *(float2*)&fh[o1] = u1;
                    // fused first_step: same thread wrote fz at o0/o1 in op 0
                    float2 z0 = *(const float2*)&fz[o0];
                    float2 z1 = *(const float2*)&fz[o1];
                    float2 w0 = make_float2(sigm(z0.x)*tanhf(u0.x), sigm(z0.y)*tanhf(u0.y));
                    float2 w1 = make_float2(sigm(z1.x)*tanhf(u1.x), sigm(z1.y)*tanhf(u1.y));
                    if (r0 == 0) w0 = make_float2(0.f, 0.f);   // null message row
                    *(float2*)&h1[o0] = w0;
                    *(float2*)&h1[o1] = w1;
                } else {
                    *(__half2*)&rx[o0] = __floats2half2_rn(u0.x, u0.y);
                    *(__half2*)&rx[o1] = __floats2half2_rn(u1.x, u1.y);
                }
            }
    }
}

// ================= MODE1 (GRU step, dual K=256, MT=64) ====================
__global__ __launch_bounds__(512, 1)
void mode1_gemm(const float* __restrict__ A1,
                const __nv_bfloat16* __restrict__ B1h, const __nv_bfloat16* __restrict__ B1l,
                const float* __restrict__ A2,
                const __nv_bfloat16* __restrict__ B2h, const __nv_bfloat16* __restrict__ B2l,
                const float* __restrict__ e0, const float* __restrict__ e1,
                const float* __restrict__ e2, float* __restrict__ C)
{
    extern __shared__ char sm[];
    const int tid = threadIdx.x;
    const int rowBase = (int)blockIdx.x << 6;
    const int lane = tid & 31, wid = tid >> 5;
    const int wm = wid >> 3, wn = wid & 7;
    const int tq = lane >> 2, tr = lane & 3;

    float acc[64];
    #pragma unroll
    for (int i = 0; i < 64; ++i) acc[i] = 0.f;

    run_phase<64,2>(A1, A2, HD, B1h, B1l, B2h, B2l, acc, sm, tid, rowBase, NM);

    #pragma unroll
    for (int mi = 0; mi < 2; ++mi)
        #pragma unroll
        for (int ni = 0; ni < 4; ++ni) {
            const float* a1 = acc + ((0*2 + mi)*4 + ni)*4;
            const float* a2 = acc + ((1*2 + mi)*4 + ni)*4;
            int gcol = wn*32 + ni*8 + tr*2;
            int r0 = rowBase + wm*32 + mi*16 + tq;
            size_t o0 = (size_t)r0*HD + gcol;
            size_t o1 = (size_t)(r0+8)*HD + gcol;
            float2 za = *(const float2*)&e0[o0];
            float2 zb = *(const float2*)&e0[o1];
            float2 ha = *(const float2*)&e1[o0];
            float2 hb = *(const float2*)&e1[o1];
            float2 sa = *(const float2*)&e2[o0];
            float2 sb = *(const float2*)&e2[o1];
            float z0 = sigm(za.x + a1[0]);
            float z1 = sigm(za.y + a1[1]);
            float z2 = sigm(zb.x + a1[2]);
            float z3 = sigm(zb.y + a1[3]);
            float p0 = tanhf(ha.x + a2[0]);
            float p1 = tanhf(ha.y + a2[1]);
            float p2 = tanhf(hb.x + a2[2]);
            float p3 = tanhf(hb.y + a2[3]);
            float2 u0 = make_float2((1.f - z0)*sa.x + z0*p0, (1.f - z1)*sa.y + z1*p1);
            float2 u1 = make_float2((1.f - z2)*sb.x + z2*p2, (1.f - z3)*sb.y + z3*p3);
            if (r0 == 0) u0 = make_float2(0.f, 0.f);
            *(float2*)&C[o0] = u0;
            *(float2*)&C[o1] = u1;
        }
}

// ================= MODE2 (output layer) ===================================
__global__ __launch_bounds__(512, 1)
void mode2_gemm(const float* __restrict__ A1, int K1,
                const __nv_bfloat16* __restrict__ B1h, const __nv_bfloat16* __restrict__ B1l,
                const float* __restrict__ A2, int K2,
                const __nv_bfloat16* __restrict__ B2h, const __nv_bfloat16* __restrict__ B2l,
                int M, const float* __restrict__ bias, const float* __restrict__ maskv,
                float* __restrict__ C)
{
    extern __shared__ char sm[];
    const int tid = threadIdx.x;
    const int rowBase = (int)blockIdx.x << 7;
    const int lane = tid & 31, wid = tid >> 5;
    const int wm = wid >> 2, wn = wid & 3;
    const int tq = lane >> 2, tr = lane & 3;

    float acc[64];
    #pragma unroll
    for (int i = 0; i < 64; ++i) acc[i] = 0.f;

    run_phase<128,1>(A1, nullptr, K1, B1h, B1l, nullptr, nullptr, acc, sm, tid, rowBase, M);
    run_phase<128,1>(A2, nullptr, K2, B2h, B2l, nullptr, nullptr, acc, sm, tid, rowBase, M);

    #pragma unroll
    for (int mi = 0; mi < 2; ++mi)
        #pragma unroll
        for (int ni = 0; ni < 8; ++ni) {
            const float* a = acc + (mi*8 + ni)*4;
            int gcol = wn*64 + ni*8 + tr*2;
            int r0 = rowBase + wm*32 + mi*16 + tq;
            float2 b = *(const float2*)&bias[gcol];
            if (r0 < M) {
                float m = maskv[r0];
                *(float2*)&C[(size_t)r0*HD + gcol] =
                    make_float2(fmaxf(a[0]+b.x, 0.f)*m, fmaxf(a[1]+b.y, 0.f)*m);
            }
            if (r0 + 8 < M) {
                float m = maskv[r0+8];
                *(float2*)&C[(size_t)(r0+8)*HD + gcol] =
                    make_float2(fmaxf(a[2]+b.x, 0.f)*m, fmaxf(a[3]+b.y, 0.f)*m);
            }
        }
}

// transpose + bf16 hi/lo split of W[K,256] -> out [N=256, K]
__global__ void prep_w(const float* __restrict__ W, __nv_bfloat16* __restrict__ oh,
                       __nv_bfloat16* __restrict__ ol, int K, int kshift)
{
    int i = blockIdx.x * blockDim.x + threadIdx.x;
    int k = i & (K - 1);
    int n = i >> kshift;
    float x = W[(size_t)k * HD + n];
    __nv_bfloat16 h = __float2bfloat16_rn(x);
    __nv_bfloat16 lo = __float2bfloat16_rn(x - __bfloat162float(h));
    oh[i] = h; ol[i] = lo;
}

__global__ void gather_msgs(const float* __restrict__ h, const __half* __restrict__ hU,
                            const __half* __restrict__ rx, const int* __restrict__ bg,
                            float* __restrict__ sumh, float* __restrict__ sumg)
{
    __shared__ int s_nb[4][NBR];
    int e = blockIdx.x * 4 + threadIdx.y;
    if (threadIdx.x < NBR) s_nb[threadIdx.y][threadIdx.x] = bg[e*NBR + threadIdx.x];
    __syncthreads();
    int c = threadIdx.x << 2;
    size_t base = (size_t)e*HD + c;
    uint2 rx4 = *(const uint2*)(rx + base);
    float2 r01 = __half22float2(*reinterpret_cast<__half2*>(&rx4.x));
    float2 r23 = __half22float2(*reinterpret_cast<__half2*>(&rx4.y));
    float4 sh = make_float4(0.f,0.f,0.f,0.f);
    float4 sg = make_float4(0.f,0.f,0.f,0.f);
    #pragma unroll
    for (int j = 0; j < NBR; ++j) {
        size_t nb = (size_t)s_nb[threadIdx.y][j]*HD + c;
        float4 hv = *(const float4*)&h[nb];
        uint2 hu4 = *(const uint2*)(hU + nb);
        float2 u01 = __half22float2(*reinterpret_cast<__half2*>(&hu4.x));
        float2 u23 = __half22float2(*reinterpret_cast<__half2*>(&hu4.y));
        sh.x += hv.x; sh.y += hv.y; sh.z += hv.z; sh.w += hv.w;
        sg.x += sigm(r01.x + u01.x) * hv.x;
        sg.y += sigm(r01.y + u01.y) * hv.y;
        sg.z += sigm(r23.x + u23.x) * hv.z;
        sg.w += sigm(r23.y + u23.y) * hv.w;
    }
    *(float4*)&sumh[base] = sh;
    *(float4*)&sumg[base] = sg;
}

__global__ void gather_nodes(const float* __restrict__ h, const int* __restrict__ ag,
                             float* __restrict__ nei)
{
    __shared__ int s_nb[4][NBR];
    int v = blockIdx.x * 4 + threadIdx.y;
    if (threadIdx.x < NBR) s_nb[threadIdx.y][threadIdx.x] = ag[v*NBR + threadIdx.x];
    __syncthreads();
    int c = threadIdx.x << 2;
    float4 s = make_float4(0.f,0.f,0.f,0.f);
    #pragma unroll
    for (int j = 0; j < NBR; ++j) {
        size_t nb = (size_t)s_nb[threadIdx.y][j]*HD + c;
        float4 hv = *(const float4*)&h[nb];
        s.x += hv.x; s.y += hv.y; s.z += hv.z; s.w += hv.w;
    }
    *(float4*)&nei[(size_t)v*HD + c] = s;
}

extern "C" void kernel_launch(void* const* d_in, const int* in_sizes, int n_in,
                              void* d_out, int out_size)
{
    const float* fnode  = (const float*)d_in[0];
    const float* fmess  = (const float*)d_in[1];
    const int*   agraph = (const int*)  d_in[2];
    const int*   bgraph = (const int*)  d_in[3];
    const float* mask   = (const float*)d_in[4];
    const float* W_z    = (const float*)d_in[5];
    const float* b_z    = (const float*)d_in[6];
    const float* W_r    = (const float*)d_in[7];
    const float* U_r    = (const float*)d_in[8];
    const float* b_ur   = (const float*)d_in[9];
    const float* W_h    = (const float*)d_in[10];
    const float* b_h    = (const float*)d_in[11];
    const float* W_o    = (const float*)d_in[12];
    const float* b_o    = (const float*)d_in[13];

    float* out_node = (float*)d_out;
    float* out_h    = out_node + (size_t)NN*HD;

    float *fz, *fh, *sumh, *sumg, *hA, *nei;
    __half *hU16, *rx16;
    __nv_bfloat16 *bh, *bl;
    cudaGetSymbolAddress((void**)&fz,   g_fz);
    cudaGetSymbolAddress((void**)&fh,   g_fh);
    cudaGetSymbolAddress((void**)&sumh, g_sumh);
    cudaGetSymbolAddress((void**)&sumg, g_sumg);
    cudaGetSymbolAddress((void**)&hA,   g_hA);
    cudaGetSymbolAddress((void**)&nei,  g_nei);
    cudaGetSymbolAddress((void**)&hU16, g_hU16);
    cudaGetSymbolAddress((void**)&rx16, g_rx16);
    cudaGetSymbolAddress((void**)&bh,   g_bh);
    cudaGetSymbolAddress((void**)&bl,   g_bl);

    cudaFuncSetAttribute((const void*)inv3_gemm,
                         cudaFuncAttributeMaxDynamicSharedMemorySize, SMEM_I3);
    cudaFuncSetAttribute((const void*)hU_gemm,
                         cudaFuncAttributeMaxDynamicSharedMemorySize, SMEM_HU);
    cudaFuncSetAttribute((const void*)mode1_gemm,
                         cudaFuncAttributeMaxDynamicSharedMemorySize, SMEM_M1);
    cudaFuncSetAttribute((const void*)mode2_gemm,
                         cudaFuncAttributeMaxDynamicSharedMemorySize, SMEM_M0);

    const int gE128 = NM / 128;               // 625
    const int gE64  = NM / 64;                // 1250
    const int gV    = NNP / 128;              // 274

    // launches 1-4: weight preps needed up front
    prep_w<<<256, 256>>>(U_r, bh+OFF_UR,  bl+OFF_UR,  HD, 8);
    prep_w<<<128, 256>>>(W_z, bh+OFF_WZT, bl+OFF_WZT, IND, 7);
    prep_w<<<128, 256>>>(W_h, bh+OFF_WHT, bl+OFF_WHT, IND, 7);
    prep_w<<<128, 256>>>(W_r, bh+OFF_WR,  bl+OFF_WR,  IND, 7);

    // launch 5: fused invariants (fz, fh, h1, rx) — first_step fused in
    inv3_gemm<<<gE128, 512, SMEM_I3>>>(fmess,
        bh+OFF_WZT, bl+OFF_WZT, bh+OFF_WHT, bl+OFF_WHT, bh+OFF_WR, bl+OFF_WR,
        b_z, b_h, b_ur, fz, fh, out_h, rx16);

    // launch 6 (profiled): single-pass hU GEMM, step d=1
    float* hc = out_h;
    float* hn = hA;
    hU_gemm<<<gE128, 512, SMEM_HU>>>(hc, bh+OFF_UR, hU16);
    gather_msgs<<<NM/4, dim3(64,4)>>>(hc, hU16, rx16, bgraph, sumh, sumg);
    // remaining preps (before first mode1 / mode2 use)
    prep_w<<<256, 256>>>(W_z + (size_t)IND*HD, bh+OFF_WZB, bl+OFF_WZB, HD, 8);
    prep_w<<<256, 256>>>(W_h + (size_t)IND*HD, bh+OFF_WHB, bl+OFF_WHB, HD, 8);
    prep_w<<<128, 256>>>(W_o,                  bh+OFF_WOT, bl+OFF_WOT, IND, 7);
    prep_w<<<256, 256>>>(W_o + (size_t)IND*HD, bh+OFF_WOB, bl+OFF_WOB, HD, 8);
    mode1_gemm<<<gE64, 512, SMEM_M1>>>(sumh, bh+OFF_WZB, bl+OFF_WZB,
                                       sumg, bh+OFF_WHB, bl+OFF_WHB,
                                       fz, fh, sumh, hn);
    { float* t = hc; hc = hn; hn = t; }

    for (int d = 2; d < DEPTH; ++d) {
        hU_gemm<<<gE128, 512, SMEM_HU>>>(hc, bh+OFF_UR, hU16);
        gather_msgs<<<NM/4, dim3(64,4)>>>(hc, hU16, rx16, bgraph, sumh, sumg);
        mode1_gemm<<<gE64, 512, SMEM_M1>>>(sumh, bh+OFF_WZB, bl+OFF_WZB,
                                           sumg, bh+OFF_WHB, bl+OFF_WHB,
                                           fz, fh, sumh, hn);
        float* t = hc; hc = hn; hn = t;
    }

    gather_nodes<<<NN/4, dim3(64,4)>>>(hc, agraph, nei);
    mode2_gemm<<<gV, 512, SMEM_M0>>>(fnode, IND, bh+OFF_WOT, bl+OFF_WOT,
                                     nei, HD, bh+OFF_WOB, bl+OFF_WOB,
                                     NN, b_o, mask, out_node);
}

// round 11
// speedup vs baseline: 1.5692x; 1.4111x over previous
#include <cuda_runtime.h>
#include <cuda_bf16.h>
#include <cuda_fp16.h>
#include <math.h>
#include <cstdint>

#define NN 35000
#define NM 80000
#define NBR 6
#define IND 128
#define HD 256
#define DEPTH 5
#define NNP 35072

// ---------------- scratch (__device__ globals; no allocs) ----------------
__device__ float g_hA  [(size_t)NM*HD];
__device__ float g_nei [(size_t)NNP*HD];
__device__ __align__(16) __half g_fz16 [(size_t)NM*HD];
__device__ __align__(16) __half g_fh16 [(size_t)NM*HD];
__device__ __align__(16) __half g_sumh16[(size_t)NM*HD];
__device__ __align__(16) __half g_sumg16[(size_t)NM*HD];
__device__ __align__(16) __half g_hU16[(size_t)NM*HD];
__device__ __align__(16) __half g_rx16[(size_t)NM*HD];
// fp16 transposed weights for the GRU-step GEMMs: [256,256]
__device__ __align__(16) __half g_wz16[65536];
__device__ __align__(16) __half g_wh16[65536];

// transposed+split bf16 weights (hi/lo planes): inv3 / hU / mode2
#define OFF_WZT 0
#define OFF_WHT 32768
#define OFF_WR  65536
#define OFF_WOT 98304
#define OFF_UR  131072
#define OFF_WOB 196608
__device__ __align__(16) __nv_bfloat16 g_bh[262144];
__device__ __align__(16) __nv_bfloat16 g_bl[262144];

__device__ __forceinline__ float sigm(float x){ return 1.0f/(1.0f+expf(-x)); }

// ---------------- mma / ldmatrix / cp.async helpers ----------------------
__device__ __forceinline__ uint32_t smem_addr(const void* p){
    return (uint32_t)__cvta_generic_to_shared(p);
}
__device__ __forceinline__ void ldsm4(uint32_t a, uint32_t& r0, uint32_t& r1,
                                      uint32_t& r2, uint32_t& r3){
    asm volatile("ldmatrix.sync.aligned.m8n8.x4.shared.b16 {%0,%1,%2,%3}, [%4];"
                 : "=r"(r0), "=r"(r1), "=r"(r2), "=r"(r3) : "r"(a));
}
__device__ __forceinline__ void mma16816(float* c, const uint32_t* a, const uint32_t* b){
    asm volatile(
        "mma.sync.aligned.m16n8k16.row.col.f32.bf16.bf16.f32 "
        "{%0,%1,%2,%3}, {%4,%5,%6,%7}, {%8,%9}, {%0,%1,%2,%3};"
        : "+f"(c[0]), "+f"(c[1]), "+f"(c[2]), "+f"(c[3])
        : "r"(a[0]), "r"(a[1]), "r"(a[2]), "r"(a[3]), "r"(b[0]), "r"(b[1]));
}
__device__ __forceinline__ void mma16816h(float* c, const uint32_t* a, const uint32_t* b){
    asm volatile(
        "mma.sync.aligned.m16n8k16.row.col.f32.f16.f16.f32 "
        "{%0,%1,%2,%3}, {%4,%5,%6,%7}, {%8,%9}, {%0,%1,%2,%3};"
        : "+f"(c[0]), "+f"(c[1]), "+f"(c[2]), "+f"(c[3])
        : "r"(a[0]), "r"(a[1]), "r"(a[2]), "r"(a[3]), "r"(b[0]), "r"(b[1]));
}
#define CPA16(dst, src) \
    asm volatile("cp.async.cg.shared.global [%0], [%1], 16;" :: "r"(dst), "l"(src))
#define CP_COMMIT() asm volatile("cp.async.commit_group;" ::: "memory")
#define CP_WAIT0()  asm volatile("cp.async.wait_group 0;" ::: "memory")
#define CP_WAIT1()  asm volatile("cp.async.wait_group 1;" ::: "memory")

__device__ __forceinline__ void cvt_split8(float4 v0, float4 v1, uint4& hi, uint4& lo){
    float f[8] = {v0.x,v0.y,v0.z,v0.w,v1.x,v1.y,v1.z,v1.w};
    uint32_t hh[8], ll[8];
    #pragma unroll
    for (int j = 0; j < 8; ++j) {
        __nv_bfloat16 h = __float2bfloat16_rn(f[j]);
        float hf = __bfloat162float(h);
        __nv_bfloat16 l = __float2bfloat16_rn(f[j] - hf);
        hh[j] = (uint32_t)__bfloat16_as_ushort(h);
        ll[j] = (uint32_t)__bfloat16_as_ushort(l);
    }
    hi = make_uint4(hh[0]|(hh[1]<<16), hh[2]|(hh[3]<<16), hh[4]|(hh[5]<<16), hh[6]|(hh[7]<<16));
    lo = make_uint4(ll[0]|(ll[1]<<16), ll[2]|(ll[3]<<16), ll[4]|(ll[5]<<16), ll[6]|(ll[7]<<16));
}
__device__ __forceinline__ uint4 cvt_hi8(float4 v0, float4 v1){
    float f[8] = {v0.x,v0.y,v0.z,v0.w,v1.x,v1.y,v1.z,v1.w};
    uint32_t hh[8];
    #pragma unroll
    for (int j = 0; j < 8; ++j)
        hh[j] = (uint32_t)__bfloat16_as_ushort(__float2bfloat16_rn(f[j]));
    return make_uint4(hh[0]|(hh[1]<<16), hh[2]|(hh[3]<<16), hh[4]|(hh[5]<<16), hh[6]|(hh[7]<<16));
}
__device__ __forceinline__ uint32_t h2u(__half2 v){ return *(uint32_t*)&v; }

#define PADK 40

// ================= 3-pass bf16 phase (mode2 only) =========================
template<int MT, int NA>
__device__ __forceinline__ void run_phase(
    const float* __restrict__ A1, const float* __restrict__ A2, int K,
    const __nv_bfloat16* __restrict__ B1h, const __nv_bfloat16* __restrict__ B1l,
    const __nv_bfloat16* __restrict__ B2h, const __nv_bfloat16* __restrict__ B2l,
    float* acc, char* sm, int tid, int rowBase, int M)
{
    constexpr int WM = MT/32;
    constexpr int WN = 16/WM;
    constexpr int NSPAN = 256/WN;
    constexpr int NFR = NSPAN/8;
    constexpr uint32_t APL = MT*80u;
    constexpr uint32_t A_BYTES = NA*2u*APL;
    constexpr uint32_t BPL = 20480u;
    constexpr uint32_t STAGE_ = A_BYTES + NA*2u*BPL;
    constexpr int NB = NA*4;
    const int lane = tid & 31, wid = tid >> 5;
    const int wm = wid / WN, wn = wid % WN;
    const int g = lane >> 3, r = lane & 7;
    const uint32_t sb = smem_addr(sm);
    const int nch = K >> 5;

    const int a_op  = tid / (MT*4);
    const int a_rem = tid % (MT*4);
    const int a_row = a_rem >> 2, a_seg = a_rem & 3;
    const int grow = rowBase + a_row;
    const bool a_ok = (grow < M);
    const float* a_src = ((a_op == 0) ? A1 : A2) + (size_t)grow*K + (a_seg << 3);
    const uint32_t a_off = (uint32_t)a_op*2u*APL + (uint32_t)a_row*80u + (uint32_t)a_seg*16u;

    auto issue_B = [&](uint32_t st, int c){
        #pragma unroll
        for (int i = 0; i < NB; ++i){
            int idx = tid + (i << 9);
            int op = idx >> 11;
            int rem = idx & 2047;
            int plane = rem >> 10;
            int rem2 = rem & 1023;
            int row = rem2 >> 2, seg = rem2 & 3;
            const __nv_bfloat16* Bp = (op == 0) ? (plane ? B1l : B1h)
                                                : (plane ? B2l : B2h);
            const __nv_bfloat16* src = Bp + (size_t)row*K + (c << 5) + (seg << 3);
            uint32_t dst = st + A_BYTES + (uint32_t)op*(2u*BPL) + (uint32_t)plane*BPL
                         + (uint32_t)row*80u + (uint32_t)seg*16u;
            CPA16(dst, src);
        }
        CP_COMMIT();
    };

    {
        float4 v0 = make_float4(0.f,0.f,0.f,0.f), v1 = v0;
        if (a_ok){ v0 = *(const float4*)a_src; v1 = *(const float4*)(a_src + 4); }
        issue_B(sb, 0);
        uint4 hi, lo; cvt_split8(v0, v1, hi, lo);
        *(uint4*)(sm + a_off)       = hi;
        *(uint4*)(sm + a_off + APL) = lo;
        CP_WAIT0();
    }
    __syncthreads();

    for (int c = 0; c < nch; ++c){
        const uint32_t st = sb + (c & 1)*STAGE_;
        const int nc = c + 1;
        float4 v0, v1;
        if (nc < nch){
            v0 = make_float4(0.f,0.f,0.f,0.f); v1 = v0;
            if (a_ok){
                const float* p = a_src + (nc << 5);
                v0 = *(const float4*)p; v1 = *(const float4*)(p + 4);
            }
            issue_B(sb + (nc & 1)*STAGE_, nc);
        }

        #pragma unroll
        for (int op = 0; op < NA; ++op){
            const uint32_t aBase = st + (uint32_t)op*2u*APL;
            const uint32_t bBase = st + A_BYTES + (uint32_t)op*(2u*BPL);
            #pragma unroll
            for (int ki = 0; ki < 2; ++ki){
                uint32_t ah[2][4], al[2][4];
                {
                    int arow = wm*32 + (g & 1)*8 + r;
                    uint32_t off = (uint32_t)(arow*PADK + ki*16 + (g >> 1)*8) * 2;
                    ldsm4(aBase + off,                   ah[0][0], ah[0][1], ah[0][2], ah[0][3]);
                    ldsm4(aBase + off + 16*PADK*2,       ah[1][0], ah[1][1], ah[1][2], ah[1][3]);
                    ldsm4(aBase + APL + off,             al[0][0], al[0][1], al[0][2], al[0][3]);
                    ldsm4(aBase + APL + off + 16*PADK*2, al[1][0], al[1][1], al[1][2], al[1][3]);
                }
                #pragma unroll
                for (int ng = 0; ng < NFR/4; ++ng){
                    uint32_t bhf[4][2], blf[4][2];
                    int nrow = wn*NSPAN + ng*32 + (g >> 1)*8 + r;
                    uint32_t off = (uint32_t)(nrow*PADK + ki*16 + (g & 1)*8) * 2;
                    ldsm4(bBase + off,                 bhf[0][0], bhf[0][1], bhf[1][0], bhf[1][1]);
                    ldsm4(bBase + off + 16*PADK*2,     bhf[2][0], bhf[2][1], bhf[3][0], bhf[3][1]);
                    ldsm4(bBase + BPL + off,             blf[0][0], blf[0][1], blf[1][0], blf[1][1]);
                    ldsm4(bBase + BPL + off + 16*PADK*2, blf[2][0], blf[2][1], blf[3][0], blf[3][1]);
                    #pragma unroll
                    for (int mi = 0; mi < 2; ++mi)
                        #pragma unroll
                        for (int j = 0; j < 4; ++j){
                            float* a = acc + (((op*2 + mi)*NFR) + ng*4 + j)*4;
                            mma16816(a, ah[mi], bhf[j]);
                            mma16816(a, ah[mi], blf[j]);
                            mma16816(a, al[mi], bhf[j]);
                        }
                }
            }
        }

        if (nc < nch){
            char* nsm = sm + (nc & 1)*STAGE_;
            uint4 hi, lo; cvt_split8(v0, v1, hi, lo);
            *(uint4*)(nsm + a_off)       = hi;
            *(uint4*)(nsm + a_off + APL) = lo;
            CP_WAIT0();
        }
        __syncthreads();
    }
}

#define SMEM_M0  (2*(2*128*80 + 2*20480))   // 122880
#define SMEM_HU  (2*(128*80 + 20480))       // 61440
#define SMEM_I3  (4*20480 + 2*40960)        // 163840
#define SMEM_M1F (3*(2*64*80 + 2*20480))    // 153600

// ================= single-pass bf16 GEMM for hU (gate path) ==============
__global__ __launch_bounds__(512, 1)
void hU_gemm(const float* __restrict__ A, const __nv_bfloat16* __restrict__ Bh,
             __half* __restrict__ Cout)
{
    constexpr int K = HD;
    constexpr uint32_t APL = 10240u, STAGE_ = 30720u;
    extern __shared__ char sm[];
    const int tid = threadIdx.x;
    const int rowBase = (int)blockIdx.x << 7;
    const int lane = tid & 31, wid = tid >> 5;
    const int wm = wid >> 2, wn = wid & 3;
    const int g = lane >> 3, r = lane & 7;
    const int tq = lane >> 2, tr = lane & 3;
    const uint32_t sb = smem_addr(sm);
    const int nch = K >> 5;

    const int a_row = tid >> 2, a_seg = tid & 3;
    const float* a_src = A + (size_t)(rowBase + a_row)*K + (a_seg << 3);
    const uint32_t a_off = (uint32_t)a_row*80u + (uint32_t)a_seg*16u;

    auto issue_B = [&](uint32_t st, int c){
        #pragma unroll
        for (int i = 0; i < 2; ++i){
            int idx = tid + (i << 9);
            int row = idx >> 2, seg = idx & 3;
            CPA16(st + APL + (uint32_t)row*80u + (uint32_t)seg*16u,
                  Bh + (size_t)row*K + (c << 5) + (seg << 3));
        }
        CP_COMMIT();
    };

    float acc[64];
    #pragma unroll
    for (int i = 0; i < 64; ++i) acc[i] = 0.f;

    {
        float4 v0 = *(const float4*)a_src;
        float4 v1 = *(const float4*)(a_src + 4);
        issue_B(sb, 0);
        *(uint4*)(sm + a_off) = cvt_hi8(v0, v1);
        CP_WAIT0();
    }
    __syncthreads();

    for (int c = 0; c < nch; ++c){
        const uint32_t st = sb + (c & 1)*STAGE_;
        const int nc = c + 1;
        float4 v0, v1;
        if (nc < nch){
            const float* p = a_src + (nc << 5);
            v0 = *(const float4*)p; v1 = *(const float4*)(p + 4);
            issue_B(sb + (nc & 1)*STAGE_, nc);
        }

        #pragma unroll
        for (int ki = 0; ki < 2; ++ki){
            uint32_t ah[2][4];
            {
                int arow = wm*32 + (g & 1)*8 + r;
                uint32_t off = (uint32_t)(arow*PADK + ki*16 + (g >> 1)*8) * 2;
                ldsm4(st + off,             ah[0][0], ah[0][1], ah[0][2], ah[0][3]);
                ldsm4(st + off + 16*PADK*2, ah[1][0], ah[1][1], ah[1][2], ah[1][3]);
            }
            #pragma unroll
            for (int ng = 0; ng < 2; ++ng){
                uint32_t bhf[4][2];
                int nrow = wn*64 + ng*32 + (g >> 1)*8 + r;
                uint32_t off = (uint32_t)(nrow*PADK + ki*16 + (g & 1)*8) * 2;
                ldsm4(st + APL + off,             bhf[0][0], bhf[0][1], bhf[1][0], bhf[1][1]);
                ldsm4(st + APL + off + 16*PADK*2, bhf[2][0], bhf[2][1], bhf[3][0], bhf[3][1]);
                #pragma unroll
                for (int mi = 0; mi < 2; ++mi)
                    #pragma unroll
                    for (int j = 0; j < 4; ++j)
                        mma16816(acc + ((mi*8) + ng*4 + j)*4, ah[mi], bhf[j]);
            }
        }

        if (nc < nch){
            *(uint4*)(sm + (nc & 1)*STAGE_ + a_off) = cvt_hi8(v0, v1);
            CP_WAIT0();
        }
        __syncthreads();
    }

    #pragma unroll
    for (int mi = 0; mi < 2; ++mi)
        #pragma unroll
        for (int ni = 0; ni < 8; ++ni){
            const float* a = acc + (mi*8 + ni)*4;
            int gcol = wn*64 + ni*8 + tr*2;
            int r0 = rowBase + wm*32 + mi*16 + tq;
            *(__half2*)&Cout[(size_t)r0*HD + gcol]     = __floats2half2_rn(a[0], a[1]);
            *(__half2*)&Cout[(size_t)(r0+8)*HD + gcol] = __floats2half2_rn(a[2], a[3]);
        }
}

// ================= fused invariants: fz16, fh16(+h1), rx16 ===============
__global__ __launch_bounds__(512, 1)
void inv3_gemm(const float* __restrict__ A,
               const __nv_bfloat16* __restrict__ Wzh, const __nv_bfloat16* __restrict__ Wzl,
               const __nv_bfloat16* __restrict__ Whh, const __nv_bfloat16* __restrict__ Whl,
               const __nv_bfloat16* __restrict__ Wrh, const __nv_bfloat16* __restrict__ Wrl,
               const float* __restrict__ b_z, const float* __restrict__ b_h,
               const float* __restrict__ b_ur,
               __half* __restrict__ fz, __half* __restrict__ fh,
               float* __restrict__ h1, __half* __restrict__ rx)
{
    constexpr int K = IND;
    constexpr uint32_t B_OFF = 81920u;
    constexpr uint32_t BPL = 20480u, BSTG = 40960u;
    extern __shared__ char sm[];
    const int tid = threadIdx.x;
    const int rowBase = (int)blockIdx.x << 7;
    const int lane = tid & 31, wid = tid >> 5;
    const int wm = wid >> 2, wn = wid & 3;
    const int g = lane >> 3, r = lane & 7;
    const int tq = lane >> 2, tr = lane & 3;
    const uint32_t sb = smem_addr(sm);

    #pragma unroll
    for (int u = 0; u < 4; ++u){
        int idx = tid + (u << 9);
        int row = idx >> 4, gi = idx & 15;
        int t = gi >> 2, seg = gi & 3;
        const float* p = A + (size_t)(rowBase + row)*K + (gi << 3);
        float4 v0 = *(const float4*)p, v1 = *(const float4*)(p + 4);
        uint4 hi, lo; cvt_split8(v0, v1, hi, lo);
        uint32_t off = (uint32_t)t*20480u + (uint32_t)row*80u + (uint32_t)seg*16u;
        *(uint4*)(sm + off)          = hi;
        *(uint4*)(sm + off + 10240u) = lo;
    }
    __syncthreads();

    const __nv_bfloat16* Bhs[3] = {Wzh, Whh, Wrh};
    const __nv_bfloat16* Bls[3] = {Wzl, Whl, Wrl};
    const float* biases[3] = {b_z, b_h, b_ur};

    #pragma unroll
    for (int op = 0; op < 3; ++op){
        const __nv_bfloat16* Bh = Bhs[op];
        const __nv_bfloat16* Bl = Bls[op];

        auto issue_B = [&](uint32_t st, int c){
            #pragma unroll
            for (int i = 0; i < 4; ++i){
                int idx = tid + (i << 9);
                int plane = idx >> 10;
                int rem = idx & 1023;
                int row = rem >> 2, seg = rem & 3;
                const __nv_bfloat16* src = (plane ? Bl : Bh)
                    + (size_t)row*K + (c << 5) + (seg << 3);
                CPA16(st + (uint32_t)plane*BPL + (uint32_t)row*80u + (uint32_t)seg*16u, src);
            }
            CP_COMMIT();
        };

        float acc[64];
        #pragma unroll
        for (int i = 0; i < 64; ++i) acc[i] = 0.f;

        issue_B(sb + B_OFF, 0);
        CP_WAIT0();
        __syncthreads();

        for (int c = 0; c < 4; ++c){
            const uint32_t aBase = sb + (uint32_t)c*20480u;
            const uint32_t bBase = sb + B_OFF + (uint32_t)(c & 1)*BSTG;
            if (c + 1 < 4) issue_B(sb + B_OFF + (uint32_t)((c+1) & 1)*BSTG, c+1);

            #pragma unroll
            for (int ki = 0; ki < 2; ++ki){
                uint32_t ah[2][4], al[2][4];
                {
                    int arow = wm*32 + (g & 1)*8 + r;
                    uint32_t off = (uint32_t)(arow*PADK + ki*16 + (g >> 1)*8) * 2;
                    ldsm4(aBase + off,                  ah[0][0], ah[0][1], ah[0][2], ah[0][3]);
                    ldsm4(aBase + off + 16*PADK*2,      ah[1][0], ah[1][1], ah[1][2], ah[1][3]);
                    ldsm4(aBase + 10240u + off,             al[0][0], al[0][1], al[0][2], al[0][3]);
                    ldsm4(aBase + 10240u + off + 16*PADK*2, al[1][0], al[1][1], al[1][2], al[1][3]);
                }
                #pragma unroll
                for (int ng = 0; ng < 2; ++ng){
                    uint32_t bhf[4][2], blf[4][2];
                    int nrow = wn*64 + ng*32 + (g >> 1)*8 + r;
                    uint32_t off = (uint32_t)(nrow*PADK + ki*16 + (g & 1)*8) * 2;
                    ldsm4(bBase + off,                 bhf[0][0], bhf[0][1], bhf[1][0], bhf[1][1]);
                    ldsm4(bBase + off + 16*PADK*2,     bhf[2][0], bhf[2][1], bhf[3][0], bhf[3][1]);
                    ldsm4(bBase + BPL + off,             blf[0][0], blf[0][1], blf[1][0], blf[1][1]);
                    ldsm4(bBase + BPL + off + 16*PADK*2, blf[2][0], blf[2][1], blf[3][0], blf[3][1]);
                    #pragma unroll
                    for (int mi = 0; mi < 2; ++mi)
                        #pragma unroll
                        for (int j = 0; j < 4; ++j){
                            float* a = acc + ((mi*8) + ng*4 + j)*4;
                            mma16816(a, ah[mi], bhf[j]);
                            mma16816(a, ah[mi], blf[j]);
                            mma16816(a, al[mi], bhf[j]);
                        }
                }
            }
            if (c + 1 < 4) CP_WAIT0();
            __syncthreads();
        }

        #pragma unroll
        for (int mi = 0; mi < 2; ++mi)
            #pragma unroll
            for (int ni = 0; ni < 8; ++ni){
                const float* a = acc + (mi*8 + ni)*4;
                int gcol = wn*64 + ni*8 + tr*2;
                int r0 = rowBase + wm*32 + mi*16 + tq;
                float2 b = *(const float2*)&biases[op][gcol];
                size_t o0 = (size_t)r0*HD + gcol;
                size_t o1 = (size_t)(r0+8)*HD + gcol;
                float2 u0 = make_float2(a[0]+b.x, a[1]+b.y);
                float2 u1 = make_float2(a[2]+b.x, a[3]+b.y);
                if (op == 0) {
                    *(__half2*)&fz[o0] = __floats2half2_rn(u0.x, u0.y);
                    *(__half2*)&fz[o1] = __floats2half2_rn(u1.x, u1.y);
                } else if (op == 1) {
                    *(__half2*)&fh[o0] = __floats2half2_rn(u0.x, u0.y);
                    *(__half2*)&fh[o1] = __floats2half2_rn(u1.x, u1.y);
                    float2 z0 = __half22float2(*(const __half2*)&fz[o0]);
                    float2 z1 = __half22float2(*(const __half2*)&fz[o1]);
                    float2 w0 = make_float2(sigm(z0.x)*tanhf(u0.x), sigm(z0.y)*tanhf(u0.y));
                    float2 w1 = make_float2(sigm(z1.x)*tanhf(u1.x), sigm(z1.y)*tanhf(u1.y));
                    if (r0 == 0) w0 = make_float2(0.f, 0.f);   // null message row
                    *(float2*)&h1[o0] = w0;
                    *(float2*)&h1[o1] = w1;
                } else {
                    *(__half2*)&rx[o0] = __floats2half2_rn(u0.x, u0.y);
                    *(__half2*)&rx[o1] = __floats2half2_rn(u1.x, u1.y);
                }
            }
    }
}

// ================= fp16 single-pass GRU-step dual GEMM ====================
// D1 = sumh16 @ Wz16^T, D2 = sumg16 @ Wh16^T (fp16 in, fp32 acc).
// h_new = ((1-z)*sumh + z*tanh(fh+D2)), z = sig(fz+D1); row 0 -> 0.
__global__ __launch_bounds__(512, 1)
void mode1f(const __half* __restrict__ A1, const __half* __restrict__ B1,
            const __half* __restrict__ A2, const __half* __restrict__ B2,
            const __half* __restrict__ fz, const __half* __restrict__ fh,
            float* __restrict__ C)
{
    constexpr int K = HD;                          // 256, 8 chunks
    constexpr uint32_t APL = 5120u, ABYTES = 10240u;
    constexpr uint32_t BPL = 20480u, STG = 51200u;
    extern __shared__ char sm[];
    const int tid = threadIdx.x;
    const int rowBase = (int)blockIdx.x << 6;      // MT=64
    const int lane = tid & 31, wid = tid >> 5;
    const int wm = wid >> 3, wn = wid & 7;         // 2 x 8 warps
    const int g = lane >> 3, r = lane & 7;
    const int tq = lane >> 2, tr = lane & 3;
    const uint32_t sb = smem_addr(sm);

    // A fill: 2 ops x 64 rows x 4 segs = 512 units = 1/thread
    const int a_op = tid >> 8, a_rem = tid & 255;
    const int a_row = a_rem >> 2, a_seg = a_rem & 3;
    const __half* a_src = ((a_op == 0) ? A1 : A2)
        + (size_t)(rowBase + a_row)*K + (a_seg << 3);
    const uint32_t a_dst = (uint32_t)a_op*APL + (uint32_t)a_row*80u + (uint32_t)a_seg*16u;

    auto issue = [&](uint32_t st, int c){
        CPA16(st + a_dst, a_src + (c << 5));
        #pragma unroll
        for (int i = 0; i < 4; ++i){
            int idx = tid + (i << 9);
            int op = idx >> 10;
            int rem = idx & 1023;
            int row = rem >> 2, seg = rem & 3;
            const __half* src = ((op == 0) ? B1 : B2)
                + (size_t)row*K + (c << 5) + (seg << 3);
            CPA16(st + ABYTES + (uint32_t)op*BPL + (uint32_t)row*80u + (uint32_t)seg*16u, src);
        }
        CP_COMMIT();
    };

    float acc[64];
    #pragma unroll
    for (int i = 0; i < 64; ++i) acc[i] = 0.f;

    issue(sb, 0);
    issue(sb + STG, 1);

    for (int c = 0; c < 8; ++c){
        if (c + 1 < 8) { CP_WAIT1(); } else { CP_WAIT0(); }
        __syncthreads();
        if (c + 2 < 8) issue(sb + ((c+2)%3)*STG, c+2);
        const uint32_t st = sb + (c%3)*STG;

        #pragma unroll
        for (int op = 0; op < 2; ++op){
            const uint32_t aBase = st + (uint32_t)op*APL;
            const uint32_t bBase = st + ABYTES + (uint32_t)op*BPL;
            #pragma unroll
            for (int ki = 0; ki < 2; ++ki){
                uint32_t ah[2][4];
                {
                    int arow = wm*32 + (g & 1)*8 + r;
                    uint32_t off = (uint32_t)(arow*PADK + ki*16 + (g >> 1)*8) * 2;
                    ldsm4(aBase + off,             ah[0][0], ah[0][1], ah[0][2], ah[0][3]);
                    ldsm4(aBase + off + 16*PADK*2, ah[1][0], ah[1][1], ah[1][2], ah[1][3]);
                }
                uint32_t bf[4][2];
                {
                    int nrow = wn*32 + (g >> 1)*8 + r;
                    uint32_t off = (uint32_t)(nrow*PADK + ki*16 + (g & 1)*8) * 2;
                    ldsm4(bBase + off,             bf[0][0], bf[0][1], bf[1][0], bf[1][1]);
                    ldsm4(bBase + off + 16*PADK*2, bf[2][0], bf[2][1], bf[3][0], bf[3][1]);
                }
                #pragma unroll
                for (int mi = 0; mi < 2; ++mi)
                    #pragma unroll
                    for (int j = 0; j < 4; ++j)
                        mma16816h(acc + ((op*2 + mi)*4 + j)*4, ah[mi], bf[j]);
            }
        }
    }

    #pragma unroll
    for (int mi = 0; mi < 2; ++mi)
        #pragma unroll
        for (int ni = 0; ni < 4; ++ni){
            const float* a1 = acc + ((0*2 + mi)*4 + ni)*4;
            const float* a2 = acc + ((1*2 + mi)*4 + ni)*4;
            int gcol = wn*32 + ni*8 + tr*2;
            int r0 = rowBase + wm*32 + mi*16 + tq;
            size_t o0 = (size_t)r0*HD + gcol;
            size_t o1 = (size_t)(r0+8)*HD + gcol;
            float2 za = __half22float2(*(const __half2*)&fz[o0]);
            float2 zb = __half22float2(*(const __half2*)&fz[o1]);
            float2 ha = __half22float2(*(const __half2*)&fh[o0]);
            float2 hb = __half22float2(*(const __half2*)&fh[o1]);
            float2 sa = __half22float2(*(const __half2*)&A1[o0]);
            float2 sb2 = __half22float2(*(const __half2*)&A1[o1]);
            float z0 = sigm(za.x + a1[0]);
            float z1 = sigm(za.y + a1[1]);
            float z2 = sigm(zb.x + a1[2]);
            float z3 = sigm(zb.y + a1[3]);
            float p0 = tanhf(ha.x + a2[0]);
            float p1 = tanhf(ha.y + a2[1]);
            float p2 = tanhf(hb.x + a2[2]);
            float p3 = tanhf(hb.y + a2[3]);
            float2 u0 = make_float2((1.f - z0)*sa.x + z0*p0, (1.f - z1)*sa.y + z1*p1);
            float2 u1 = make_float2((1.f - z2)*sb2.x + z2*p2, (1.f - z3)*sb2.y + z3*p3);
            if (r0 == 0) u0 = make_float2(0.f, 0.f);
            *(float2*)&C[o0] = u0;
            *(float2*)&C[o1] = u1;
        }
}

// ================= MODE2 (output layer, bf16 3-pass) ======================
__global__ __launch_bounds__(512, 1)
void mode2_gemm(const float* __restrict__ A1, int K1,
                const __nv_bfloat16* __restrict__ B1h, const __nv_bfloat16* __restrict__ B1l,
                const float* __restrict__ A2, int K2,
                const __nv_bfloat16* __restrict__ B2h, const __nv_bfloat16* __restrict__ B2l,
                int M, const float* __restrict__ bias, const float* __restrict__ maskv,
                float* __restrict__ C)
{
    extern __shared__ char sm[];
    const int tid = threadIdx.x;
    const int rowBase = (int)blockIdx.x << 7;
    const int lane = tid & 31, wid = tid >> 5;
    const int wm = wid >> 2, wn = wid & 3;
    const int tq = lane >> 2, tr = lane & 3;

    float acc[64];
    #pragma unroll
    for (int i = 0; i < 64; ++i) acc[i] = 0.f;

    run_phase<128,1>(A1, nullptr, K1, B1h, B1l, nullptr, nullptr, acc, sm, tid, rowBase, M);
    run_phase<128,1>(A2, nullptr, K2, B2h, B2l, nullptr, nullptr, acc, sm, tid, rowBase, M);

    #pragma unroll
    for (int mi = 0; mi < 2; ++mi)
        #pragma unroll
        for (int ni = 0; ni < 8; ++ni) {
            const float* a = acc + (mi*8 + ni)*4;
            int gcol = wn*64 + ni*8 + tr*2;
            int r0 = rowBase + wm*32 + mi*16 + tq;
            float2 b = *(const float2*)&bias[gcol];
            if (r0 < M) {
                float m = maskv[r0];
                *(float2*)&C[(size_t)r0*HD + gcol] =
                    make_float2(fmaxf(a[0]+b.x, 0.f)*m, fmaxf(a[1]+b.y, 0.f)*m);
            }
            if (r0 + 8 < M) {
                float m = maskv[r0+8];
                *(float2*)&C[(size_t)(r0+8)*HD + gcol] =
                    make_float2(fmaxf(a[2]+b.x, 0.f)*m, fmaxf(a[3]+b.y, 0.f)*m);
            }
        }
}

// transpose + bf16 hi/lo split of W[K,256] -> [256,K]
__global__ void prep_w(const float* __restrict__ W, __nv_bfloat16* __restrict__ oh,
                       __nv_bfloat16* __restrict__ ol, int K, int kshift)
{
    int i = blockIdx.x * blockDim.x + threadIdx.x;
    int k = i & (K - 1);
    int n = i >> kshift;
    float x = W[(size_t)k * HD + n];
    __nv_bfloat16 h = __float2bfloat16_rn(x);
    __nv_bfloat16 lo = __float2bfloat16_rn(x - __bfloat162float(h));
    oh[i] = h; ol[i] = lo;
}

// transpose to fp16 [256,K]
__global__ void prep_w16(const float* __restrict__ W, __half* __restrict__ o,
                         int K, int kshift)
{
    int i = blockIdx.x * blockDim.x + threadIdx.x;
    int k = i & (K - 1);
    int n = i >> kshift;
    o[i] = __float2half_rn(W[(size_t)k * HD + n]);
}

__global__ void gather_msgs(const float* __restrict__ h, const __half* __restrict__ hU,
                            const __half* __restrict__ rx, const int* __restrict__ bg,
                            __half* __restrict__ sumh, __half* __restrict__ sumg)
{
    __shared__ int s_nb[4][NBR];
    int e = blockIdx.x * 4 + threadIdx.y;
    if (threadIdx.x < NBR) s_nb[threadIdx.y][threadIdx.x] = bg[e*NBR + threadIdx.x];
    __syncthreads();
    int c = threadIdx.x << 2;
    size_t base = (size_t)e*HD + c;
    uint2 rx4 = *(const uint2*)(rx + base);
    float2 r01 = __half22float2(*reinterpret_cast<__half2*>(&rx4.x));
    float2 r23 = __half22float2(*reinterpret_cast<__half2*>(&rx4.y));
    float4 sh = make_float4(0.f,0.f,0.f,0.f);
    float4 sg = make_float4(0.f,0.f,0.f,0.f);
    #pragma unroll
    for (int j = 0; j < NBR; ++j) {
        size_t nb = (size_t)s_nb[threadIdx.y][j]*HD + c;
        float4 hv = *(const float4*)&h[nb];
        uint2 hu4 = *(const uint2*)(hU + nb);
        float2 u01 = __half22float2(*reinterpret_cast<__half2*>(&hu4.x));
        float2 u23 = __half22float2(*reinterpret_cast<__half2*>(&hu4.y));
        sh.x += hv.x; sh.y += hv.y; sh.z += hv.z; sh.w += hv.w;
        sg.x += sigm(r01.x + u01.x) * hv.x;
        sg.y += sigm(r01.y + u01.y) * hv.y;
        sg.z += sigm(r23.x + u23.x) * hv.z;
        sg.w += sigm(r23.y + u23.y) * hv.w;
    }
    __half2 sh01 = __floats2half2_rn(sh.x, sh.y), sh23 = __floats2half2_rn(sh.z, sh.w);
    __half2 sg01 = __floats2half2_rn(sg.x, sg.y), sg23 = __floats2half2_rn(sg.z, sg.w);
    *(uint2*)(sumh + base) = make_uint2(h2u(sh01), h2u(sh23));
    *(uint2*)(sumg + base) = make_uint2(h2u(sg01), h2u(sg23));
}

__global__ void gather_nodes(const float* __restrict__ h, const int* __restrict__ ag,
                             float* __restrict__ nei)
{
    __shared__ int s_nb[4][NBR];
    int v = blockIdx.x * 4 + threadIdx.y;
    if (threadIdx.x < NBR) s_nb[threadIdx.y][threadIdx.x] = ag[v*NBR + threadIdx.x];
    __syncthreads();
    int c = threadIdx.x << 2;
    float4 s = make_float4(0.f,0.f,0.f,0.f);
    #pragma unroll
    for (int j = 0; j < NBR; ++j) {
        size_t nb = (size_t)s_nb[threadIdx.y][j]*HD + c;
        float4 hv = *(const float4*)&h[nb];
        s.x += hv.x; s.y += hv.y; s.z += hv.z; s.w += hv.w;
    }
    *(float4*)&nei[(size_t)v*HD + c] = s;
}

extern "C" void kernel_launch(void* const* d_in, const int* in_sizes, int n_in,
                              void* d_out, int out_size)
{
    const float* fnode  = (const float*)d_in[0];
    const float* fmess  = (const float*)d_in[1];
    const int*   agraph = (const int*)  d_in[2];
    const int*   bgraph = (const int*)  d_in[3];
    const float* mask   = (const float*)d_in[4];
    const float* W_z    = (const float*)d_in[5];
    const float* b_z    = (const float*)d_in[6];
    const float* W_r    = (const float*)d_in[7];
    const float* U_r    = (const float*)d_in[8];
    const float* b_ur   = (const float*)d_in[9];
    const float* W_h    = (const float*)d_in[10];
    const float* b_h    = (const float*)d_in[11];
    const float* W_o    = (const float*)d_in[12];
    const float* b_o    = (const float*)d_in[13];

    float* out_node = (float*)d_out;
    float* out_h    = out_node + (size_t)NN*HD;

    float *hA, *nei;
    __half *fz16, *fh16, *sumh16, *sumg16, *hU16, *rx16, *wz16, *wh16;
    __nv_bfloat16 *bh, *bl;
    cudaGetSymbolAddress((void**)&hA,     g_hA);
    cudaGetSymbolAddress((void**)&nei,    g_nei);
    cudaGetSymbolAddress((void**)&fz16,   g_fz16);
    cudaGetSymbolAddress((void**)&fh16,   g_fh16);
    cudaGetSymbolAddress((void**)&sumh16, g_sumh16);
    cudaGetSymbolAddress((void**)&sumg16, g_sumg16);
    cudaGetSymbolAddress((void**)&hU16,   g_hU16);
    cudaGetSymbolAddress((void**)&rx16,   g_rx16);
    cudaGetSymbolAddress((void**)&wz16,   g_wz16);
    cudaGetSymbolAddress((void**)&wh16,   g_wh16);
    cudaGetSymbolAddress((void**)&bh,     g_bh);
    cudaGetSymbolAddress((void**)&bl,     g_bl);

    cudaFuncSetAttribute((const void*)inv3_gemm,
                         cudaFuncAttributeMaxDynamicSharedMemorySize, SMEM_I3);
    cudaFuncSetAttribute((const void*)hU_gemm,
                         cudaFuncAttributeMaxDynamicSharedMemorySize, SMEM_HU);
    cudaFuncSetAttribute((const void*)mode1f,
                         cudaFuncAttributeMaxDynamicSharedMemorySize, SMEM_M1F);
    cudaFuncSetAttribute((const void*)mode2_gemm,
                         cudaFuncAttributeMaxDynamicSharedMemorySize, SMEM_M0);

    const int gE128 = NM / 128;               // 625
    const int gE64  = NM / 64;                // 1250
    const int gV    = NNP / 128;              // 274

    // weight preps
    prep_w<<<256, 256>>>(U_r, bh+OFF_UR,  bl+OFF_UR,  HD, 8);
    prep_w<<<128, 256>>>(W_z, bh+OFF_WZT, bl+OFF_WZT, IND, 7);
    prep_w<<<128, 256>>>(W_h, bh+OFF_WHT, bl+OFF_WHT, IND, 7);
    prep_w<<<128, 256>>>(W_r, bh+OFF_WR,  bl+OFF_WR,  IND, 7);

    // fused invariants (fz16, fh16, h1, rx16)
    inv3_gemm<<<gE128, 512, SMEM_I3>>>(fmess,
        bh+OFF_WZT, bl+OFF_WZT, bh+OFF_WHT, bl+OFF_WHT, bh+OFF_WR, bl+OFF_WR,
        b_z, b_h, b_ur, fz16, fh16, out_h, rx16);

    // fp16 weight preps for the GRU-step GEMMs (+ output-layer preps)
    prep_w16<<<256, 256>>>(W_z + (size_t)IND*HD, wz16, HD, 8);
    prep_w16<<<256, 256>>>(W_h + (size_t)IND*HD, wh16, HD, 8);
    prep_w<<<128, 256>>>(W_o,                  bh+OFF_WOT, bl+OFF_WOT, IND, 7);
    prep_w<<<256, 256>>>(W_o + (size_t)IND*HD, bh+OFF_WOB, bl+OFF_WOB, HD, 8);

    float* hc = out_h;
    float* hn = hA;
    for (int d = 1; d < DEPTH; ++d) {
        hU_gemm<<<gE128, 512, SMEM_HU>>>(hc, bh+OFF_UR, hU16);
        gather_msgs<<<NM/4, dim3(64,4)>>>(hc, hU16, rx16, bgraph, sumh16, sumg16);
        mode1f<<<gE64, 512, SMEM_M1F>>>(sumh16, wz16, sumg16, wh16,
                                        fz16, fh16, hn);
        float* t = hc; hc = hn; hn = t;
    }

    gather_nodes<<<NN/4, dim3(64,4)>>>(hc, agraph, nei);
    mode2_gemm<<<gV, 512, SMEM_M0>>>(fnode, IND, bh+OFF_WOT, bl+OFF_WOT,
                                     nei, HD, bh+OFF_WOB, bl+OFF_WOB,
                                     NN, b_o, mask, out_node);
}